// round 8
// baseline (speedup 1.0000x reference)
#include <cuda_runtime.h>
#include <math.h>

#define SEQ    2048
#define NQKV   6144
#define HID    2048

typedef unsigned long long u64;

// ------------------------- scratch (device globals) -------------------------
__device__ float g_qkv [(size_t)2 * SEQ * NQKV];          // [b*s][6144]
__device__ float g_q   [(size_t)32 * 128 * SEQ];          // [bh][d][s]
__device__ float g_k   [(size_t)32 * 128 * SEQ];          // [bh][d][s]
__device__ float g_v   [(size_t)32 * SEQ * 128];          // [bh][s][d]
__device__ float g_attn[(size_t)2 * SEQ * HID];           // [b*s][2048]

// ------------------------- f32x2 helpers -------------------------
__device__ __forceinline__ void ffma2(u64 &d, u64 a, u64 b) {
    asm("fma.rn.f32x2 %0, %1, %2, %0;" : "+l"(d) : "l"(a), "l"(b));
}
__device__ __forceinline__ void fmul2(u64 &d, u64 a) {
    asm("mul.rn.f32x2 %0, %0, %1;" : "+l"(d) : "l"(a));
}
__device__ __forceinline__ u64 pack2(float x, float y) {
    u64 r; asm("mov.b64 %0, {%1, %2};" : "=l"(r) : "f"(x), "f"(y)); return r;
}
__device__ __forceinline__ float2 unpack2(u64 v) {
    float2 f; asm("mov.b64 {%0, %1}, %2;" : "=f"(f.x), "=f"(f.y) : "l"(v)); return f;
}

// ---------------------------------------------------------------------------
// SGEMM: C[M,N] = A[M,K] @ B[K,N] + bias[N].  128x128 tile, BK=16, 256 thr,
// 8x8 per thread.  A stored DUPLICATED in smem so the f32x2 inner loop has
// naturally packed operands on both sides (no pack MOVs).
// ---------------------------------------------------------------------------
__global__ __launch_bounds__(256, 2)
void sgemm128(const float* __restrict__ A, const float* __restrict__ B,
              const float* __restrict__ bias, float* __restrict__ C,
              int M, int N, int K)
{
    __shared__ __align__(16) float As2[16][256];   // As2[k][2m],[2m+1] = A[m][k]
    __shared__ __align__(16) float Bs [16][128];

    const int tid = threadIdx.x;
    const int tx = tid & 15, ty = tid >> 4;
    const int rowBase = blockIdx.y * 128, colBase = blockIdx.x * 128;

    const int ar = tid >> 2;           // 0..63 (+64)
    const int ak = (tid & 3) * 4;      // 0,4,8,12
    const int br = tid >> 5;           // 0..7 (+8)
    const int bn = (tid & 31) * 4;

    const float* Ap = A + (size_t)(rowBase + ar) * K + ak;
    const float* Bp = B + (size_t)br * N + colBase + bn;

    float4 pa0 = *(const float4*)Ap;
    float4 pa1 = *(const float4*)(Ap + (size_t)64 * K);
    float4 pb0 = *(const float4*)Bp;
    float4 pb1 = *(const float4*)(Bp + (size_t)8 * N);

    u64 acc[8][4];
#pragma unroll
    for (int i = 0; i < 8; i++)
#pragma unroll
        for (int j = 0; j < 4; j++) acc[i][j] = 0ull;

    const int iters = K >> 4;
    for (int it = 0; it < iters; ++it) {
        // store prefetched tiles (A duplicated + transposed)
        {
            float a0[4], a1[4];
            *(float4*)a0 = pa0; *(float4*)a1 = pa1;
#pragma unroll
            for (int t = 0; t < 4; t++) {
                *(u64*)&As2[ak + t][2 * ar]       = pack2(a0[t], a0[t]);
                *(u64*)&As2[ak + t][2 * ar + 128] = pack2(a1[t], a1[t]);
            }
            *(float4*)&Bs[br][bn]     = pb0;
            *(float4*)&Bs[br + 8][bn] = pb1;
        }
        __syncthreads();

        if (it + 1 < iters) {
            const float* An = Ap + (it + 1) * 16;
            const float* Bn = Bp + (size_t)(it + 1) * 16 * N;
            pa0 = *(const float4*)An;
            pa1 = *(const float4*)(An + (size_t)64 * K);
            pb0 = *(const float4*)Bn;
            pb1 = *(const float4*)(Bn + (size_t)8 * N);
        }

#pragma unroll
        for (int kk = 0; kk < 16; kk++) {
            ulonglong2 a01 = *(const ulonglong2*)&As2[kk][ty * 16];
            ulonglong2 a23 = *(const ulonglong2*)&As2[kk][ty * 16 + 4];
            ulonglong2 a45 = *(const ulonglong2*)&As2[kk][ty * 16 + 8];
            ulonglong2 a67 = *(const ulonglong2*)&As2[kk][ty * 16 + 12];
            ulonglong2 b01 = *(const ulonglong2*)&Bs[kk][tx * 4];
            ulonglong2 b23 = *(const ulonglong2*)&Bs[kk][64 + tx * 4];
            u64 ad[8] = {a01.x, a01.y, a23.x, a23.y, a45.x, a45.y, a67.x, a67.y};
            u64 bp[4] = {b01.x, b01.y, b23.x, b23.y};
#pragma unroll
            for (int i = 0; i < 8; i++) {
                ffma2(acc[i][0], ad[i], bp[0]);
                ffma2(acc[i][1], ad[i], bp[1]);
                ffma2(acc[i][2], ad[i], bp[2]);
                ffma2(acc[i][3], ad[i], bp[3]);
            }
        }
        __syncthreads();
    }

    float4 bb0 = *(const float4*)&bias[colBase + tx * 4];
    float4 bb1 = *(const float4*)&bias[colBase + 64 + tx * 4];
#pragma unroll
    for (int i = 0; i < 8; i++) {
        float* cp = C + (size_t)(rowBase + ty * 8 + i) * N + colBase;
        float2 f0 = unpack2(acc[i][0]), f1 = unpack2(acc[i][1]);
        float2 f2 = unpack2(acc[i][2]), f3 = unpack2(acc[i][3]);
        float4 r0 = make_float4(f0.x + bb0.x, f0.y + bb0.y, f1.x + bb0.z, f1.y + bb0.w);
        float4 r1 = make_float4(f2.x + bb1.x, f2.y + bb1.y, f3.x + bb1.z, f3.y + bb1.w);
        *(float4*)&cp[tx * 4]      = r0;
        *(float4*)&cp[64 + tx * 4] = r1;
    }
}

// ---------------------------------------------------------------------------
// RoPE + scatter: g_qkv [b*s][h*384+{q,k,v}] -> Q,K as [bh][d][s], V [bh][s][d]
// Q pre-scaled by 1/sqrt(128).  ROT=32, half=16.
// ---------------------------------------------------------------------------
__global__ void rope_scatter(const float* __restrict__ qkv,
                             float* __restrict__ q, float* __restrict__ k,
                             float* __restrict__ v)
{
    const int s  = blockIdx.x;
    const int bh = blockIdx.y;
    const int b  = bh >> 4, h = bh & 15;
    const int d  = threadIdx.x;  // 0..127

    const float* src = qkv + ((size_t)(b * SEQ + s)) * NQKV + h * 384;
    float qv = src[d];
    float kv = src[128 + d];
    float vv = src[256 + d];

    if (d < 32) {
        const int i = d & 15;
        float invf = expf(-(float)i * (9.210340371976184f / 16.0f)); // 10000^(-i/16)
        float sn, cs;
        sincosf((float)s * invf, &sn, &cs);
        float q2 = (d < 16) ? -src[d + 16]       : src[d - 16];
        float k2 = (d < 16) ? -src[128 + d + 16] : src[128 + d - 16];
        qv = qv * cs + q2 * sn;
        kv = kv * cs + k2 * sn;
    }
    qv *= 0.08838834764831843f;  // 1/sqrt(128)

    size_t tb = (size_t)bh * 128 * SEQ + (size_t)d * SEQ + s;
    q[tb] = qv;
    k[tb] = kv;
    v[(size_t)bh * SEQ * 128 + (size_t)s * 128 + d] = vv;
}

// ---------------------------------------------------------------------------
// Flash attention, fp32 causal.  BQ=BKV=64, D=128, 256 threads (16x16).
// Qs and Ps stored duplicated in smem -> both GEMM loops run on FFMA2.
// Writes attn into g_attn [b*s][h*128+d].
// ---------------------------------------------------------------------------
#define FL_SMEM_FLOATS (128*128 + 128*64 + 64*128 + 64*140)
#define FL_SMEM_BYTES  (FL_SMEM_FLOATS * 4)

__global__ __launch_bounds__(256)
void flash_kernel(const float* __restrict__ gq_all, const float* __restrict__ gk_all,
                  const float* __restrict__ gv_all, float* __restrict__ out)
{
    extern __shared__ __align__(16) float sm[];
    float* Qs2 = sm;               // [128][128]  dup over q
    float* Ks  = sm + 16384;       // [128][64]
    float* Vs  = sm + 24576;       // [64][128]
    float* Ps2 = sm + 32768;       // [64][140]   dup over k, padded

    const int tid = threadIdx.x;
    const int tx = tid & 15, ty = tid >> 4;
    const int qt = 31 - (int)blockIdx.x;     // heavy tiles first
    const int bh = blockIdx.y;
    const int q0 = qt << 6;

    const float* gq = gq_all + (size_t)bh * 128 * SEQ;
    const float* gk = gk_all + (size_t)bh * 128 * SEQ;
    const float* gv = gv_all + (size_t)bh * SEQ * 128;

    // load Q tile duplicated: Qs2[d][2q],[2q+1]
    {
        const int c = tx * 4;
#pragma unroll
        for (int p = 0; p < 8; p++) {
            int d = p * 16 + ty;
            float4 v = *(const float4*)&gq[(size_t)d * SEQ + q0 + c];
            *(float4*)&Qs2[d * 128 + 2 * c]     = make_float4(v.x, v.x, v.y, v.y);
            *(float4*)&Qs2[d * 128 + 2 * c + 4] = make_float4(v.z, v.z, v.w, v.w);
        }
    }

    u64 acc[4][4];
#pragma unroll
    for (int i = 0; i < 4; i++)
#pragma unroll
        for (int j = 0; j < 4; j++) acc[i][j] = 0ull;
    float mrun[4] = {-1e30f, -1e30f, -1e30f, -1e30f};
    float lrun[4] = {0.f, 0.f, 0.f, 0.f};

    for (int kt = 0; kt <= qt; kt++) {
        __syncthreads();   // previous PV reads done before overwriting K/V
        {
            const int c = tx * 4;
#pragma unroll
            for (int p = 0; p < 8; p++) {
                int d = p * 16 + ty;
                *(float4*)&Ks[d * 64 + c] =
                    *(const float4*)&gk[(size_t)d * SEQ + kt * 64 + c];
            }
            const int r2 = tid >> 5, c2 = (tid & 31) * 4;
#pragma unroll
            for (int p = 0; p < 8; p++) {
                int row = p * 8 + r2;
                *(float4*)&Vs[row * 128 + c2] =
                    *(const float4*)&gv[(size_t)(kt * 64 + row) * 128 + c2];
            }
        }
        __syncthreads();

        // ---- S = Q^T K (FFMA2) ----
        u64 s2[4][2];
#pragma unroll
        for (int i = 0; i < 4; i++) { s2[i][0] = 0ull; s2[i][1] = 0ull; }
#pragma unroll 8
        for (int d = 0; d < 128; d++) {
            ulonglong2 a01 = *(const ulonglong2*)&Qs2[d * 128 + ty * 8];
            ulonglong2 a23 = *(const ulonglong2*)&Qs2[d * 128 + ty * 8 + 4];
            ulonglong2 bb  = *(const ulonglong2*)&Ks[d * 64 + tx * 4];
            ffma2(s2[0][0], a01.x, bb.x); ffma2(s2[0][1], a01.x, bb.y);
            ffma2(s2[1][0], a01.y, bb.x); ffma2(s2[1][1], a01.y, bb.y);
            ffma2(s2[2][0], a23.x, bb.x); ffma2(s2[2][1], a23.x, bb.y);
            ffma2(s2[3][0], a23.y, bb.x); ffma2(s2[3][1], a23.y, bb.y);
        }

        float s[4][4];
#pragma unroll
        for (int i = 0; i < 4; i++) {
            float2 u0 = unpack2(s2[i][0]), u1 = unpack2(s2[i][1]);
            s[i][0] = u0.x; s[i][1] = u0.y; s[i][2] = u1.x; s[i][3] = u1.y;
        }

        // causal mask (diagonal tile only)
        if (kt == qt) {
#pragma unroll
            for (int i = 0; i < 4; i++)
#pragma unroll
                for (int j = 0; j < 4; j++)
                    if (kt * 64 + tx * 4 + j > q0 + ty * 4 + i) s[i][j] = -1e30f;
        }

        // ---- online softmax ----
        float p[4][4], scale[4];
#pragma unroll
        for (int i = 0; i < 4; i++) {
            float m = fmaxf(fmaxf(s[i][0], s[i][1]), fmaxf(s[i][2], s[i][3]));
#pragma unroll
            for (int off = 8; off >= 1; off >>= 1)
                m = fmaxf(m, __shfl_xor_sync(0xffffffffu, m, off, 16));
            float mn = fmaxf(mrun[i], m);
            scale[i] = __expf(mrun[i] - mn);
            mrun[i] = mn;
            float l = 0.f;
#pragma unroll
            for (int j = 0; j < 4; j++) { p[i][j] = __expf(s[i][j] - mn); l += p[i][j]; }
#pragma unroll
            for (int off = 8; off >= 1; off >>= 1)
                l += __shfl_xor_sync(0xffffffffu, l, off, 16);
            lrun[i] = lrun[i] * scale[i] + l;
        }
#pragma unroll
        for (int i = 0; i < 4; i++) {
            u64 sd = pack2(scale[i], scale[i]);
            fmul2(acc[i][0], sd); fmul2(acc[i][1], sd);
            fmul2(acc[i][2], sd); fmul2(acc[i][3], sd);
        }

        // write P duplicated: Ps2[q][2k],[2k+1]
#pragma unroll
        for (int i = 0; i < 4; i++)
#pragma unroll
            for (int j = 0; j < 4; j++)
                *(u64*)&Ps2[(ty * 4 + i) * 140 + (tx * 4 + j) * 2] = pack2(p[i][j], p[i][j]);
        __syncthreads();

        // ---- O += P V (FFMA2) ----
#pragma unroll 4
        for (int kk2 = 0; kk2 < 32; kk2++) {
            const int kk = kk2 * 2;
            ulonglong2 pv[4];
#pragma unroll
            for (int i = 0; i < 4; i++)
                pv[i] = *(const ulonglong2*)&Ps2[(ty * 4 + i) * 140 + kk2 * 4];
            ulonglong2 va = *(const ulonglong2*)&Vs[kk * 128 + tx * 4];
            ulonglong2 vb = *(const ulonglong2*)&Vs[kk * 128 + 64 + tx * 4];
            ulonglong2 vc = *(const ulonglong2*)&Vs[(kk + 1) * 128 + tx * 4];
            ulonglong2 vd = *(const ulonglong2*)&Vs[(kk + 1) * 128 + 64 + tx * 4];
#pragma unroll
            for (int i = 0; i < 4; i++) {
                ffma2(acc[i][0], pv[i].x, va.x); ffma2(acc[i][1], pv[i].x, va.y);
                ffma2(acc[i][2], pv[i].x, vb.x); ffma2(acc[i][3], pv[i].x, vb.y);
                ffma2(acc[i][0], pv[i].y, vc.x); ffma2(acc[i][1], pv[i].y, vc.y);
                ffma2(acc[i][2], pv[i].y, vd.x); ffma2(acc[i][3], pv[i].y, vd.y);
            }
        }
    }

    // ---- normalize + store ----
    const int b = bh >> 4, h = bh & 15;
#pragma unroll
    for (int i = 0; i < 4; i++) {
        float inv = 1.0f / lrun[i];
        int q = q0 + ty * 4 + i;
        float* op = out + ((size_t)(b * SEQ + q)) * HID + h * 128;
        float2 f0 = unpack2(acc[i][0]), f1 = unpack2(acc[i][1]);
        float2 f2 = unpack2(acc[i][2]), f3 = unpack2(acc[i][3]);
        *(float4*)&op[tx * 4] =
            make_float4(f0.x * inv, f0.y * inv, f1.x * inv, f1.y * inv);
        *(float4*)&op[64 + tx * 4] =
            make_float4(f2.x * inv, f2.y * inv, f3.x * inv, f3.y * inv);
    }
}

// ---------------------------------------------------------------------------
extern "C" void kernel_launch(void* const* d_in, const int* in_sizes, int n_in,
                              void* d_out, int out_size)
{
    const float* hidden = (const float*)d_in[0];
    // d_in[1] = attention_mask (causal by construction; implemented directly)
    const float* qkvk = (const float*)d_in[2];
    const float* qkvb = (const float*)d_in[3];
    const float* outk = (const float*)d_in[4];
    const float* outb = (const float*)d_in[5];
    float* out = (float*)d_out;

    float *pqkv, *pq, *pk, *pv, *pattn;
    cudaGetSymbolAddress((void**)&pqkv,  g_qkv);
    cudaGetSymbolAddress((void**)&pq,    g_q);
    cudaGetSymbolAddress((void**)&pk,    g_k);
    cudaGetSymbolAddress((void**)&pv,    g_v);
    cudaGetSymbolAddress((void**)&pattn, g_attn);

    cudaFuncSetAttribute((const void*)flash_kernel,
                         cudaFuncAttributeMaxDynamicSharedMemorySize, FL_SMEM_BYTES);

    // 1) QKV projection: [4096,2048] @ [2048,6144] + bias
    sgemm128<<<dim3(48, 32), 256>>>(hidden, qkvk, qkvb, pqkv, 4096, 6144, 2048);
    // 2) RoPE + scatter to flash-friendly layouts
    rope_scatter<<<dim3(SEQ, 32), 128>>>(pqkv, pq, pk, pv);
    // 3) causal flash attention
    flash_kernel<<<dim3(32, 32), 256, FL_SMEM_BYTES>>>(pq, pk, pv, pattn);
    // 4) output projection: [4096,2048] @ [2048,2048] + bias
    sgemm128<<<dim3(16, 32), 256>>>(pattn, outk, outb, out, 4096, 2048, 2048);
}

// round 10
// speedup vs baseline: 1.6957x; 1.6957x over previous
#include <cuda_runtime.h>
#include <cuda_bf16.h>
#include <math.h>
#include <stdint.h>

#define SEQ    2048
#define NQKV   6144
#define HID    2048

typedef unsigned long long u64;
typedef unsigned int u32;

// ------------------------- scratch (device globals) -------------------------
__device__ float g_qkv [(size_t)2 * SEQ * NQKV];          // [b*s][6144]
__device__ float g_q   [(size_t)32 * 128 * SEQ];          // [bh][d][s]
__device__ float g_k   [(size_t)32 * 128 * SEQ];          // [bh][d][s]
__device__ float g_v   [(size_t)32 * SEQ * 128];          // [bh][s][d]
__device__ float g_attn[(size_t)2 * SEQ * HID];           // [b*s][2048]
__device__ __nv_bfloat16 g_ah[(size_t)4096 * 2048];       // A hi  [M][K]
__device__ __nv_bfloat16 g_al[(size_t)4096 * 2048];       // A lo
__device__ __nv_bfloat16 g_bh[(size_t)6144 * 2048];       // B^T hi [N][K]
__device__ __nv_bfloat16 g_bl[(size_t)6144 * 2048];       // B^T lo

// ------------------------- f32x2 helpers (flash) -------------------------
__device__ __forceinline__ void ffma2(u64 &d, u64 a, u64 b) {
    asm("fma.rn.f32x2 %0, %1, %2, %0;" : "+l"(d) : "l"(a), "l"(b));
}
__device__ __forceinline__ void fmul2(u64 &d, u64 a) {
    asm("mul.rn.f32x2 %0, %0, %1;" : "+l"(d) : "l"(a));
}
__device__ __forceinline__ u64 pack2(float x, float y) {
    u64 r; asm("mov.b64 %0, {%1, %2};" : "=l"(r) : "f"(x), "f"(y)); return r;
}
__device__ __forceinline__ float2 unpack2(u64 v) {
    float2 f; asm("mov.b64 {%0, %1}, %2;" : "=f"(f.x), "=f"(f.y) : "l"(v)); return f;
}

// ------------------------- async / mma helpers (base PTX only) ---------------
__device__ __forceinline__ void cpa16(u32 dst, const void* src) {
    asm volatile("cp.async.cg.shared.global [%0], [%1], 16;" :: "r"(dst), "l"(src));
}
__device__ __forceinline__ void ldsm4(u32 r[4], u32 addr) {
    asm volatile("ldmatrix.sync.aligned.m8n8.x4.shared.b16 {%0,%1,%2,%3}, [%4];"
                 : "=r"(r[0]), "=r"(r[1]), "=r"(r[2]), "=r"(r[3]) : "r"(addr));
}
__device__ __forceinline__ void mma_bf16(float c[4], const u32 a[4], const u32 b[2]) {
    asm volatile("mma.sync.aligned.m16n8k16.row.col.f32.bf16.bf16.f32 "
                 "{%0,%1,%2,%3}, {%4,%5,%6,%7}, {%8,%9}, {%0,%1,%2,%3};"
                 : "+f"(c[0]), "+f"(c[1]), "+f"(c[2]), "+f"(c[3])
                 : "r"(a[0]), "r"(a[1]), "r"(a[2]), "r"(a[3]), "r"(b[0]), "r"(b[1]));
}

// ---------------------------------------------------------------------------
// Split kernels: fp32 -> (bf16 hi, bf16 lo)
// ---------------------------------------------------------------------------
__global__ void split_rm(const float4* __restrict__ x, __nv_bfloat16* __restrict__ hi,
                         __nv_bfloat16* __restrict__ lo, int n4)
{
    int i = blockIdx.x * 256 + threadIdx.x;
    if (i >= n4) return;
    float4 v = x[i];
    float a[4] = {v.x, v.y, v.z, v.w};
    __nv_bfloat16 H[4], L[4];
#pragma unroll
    for (int j = 0; j < 4; j++) {
        H[j] = __float2bfloat16(a[j]);
        L[j] = __float2bfloat16(a[j] - __bfloat162float(H[j]));
    }
    *(uint2*)(hi + 4 * (size_t)i) = *(uint2*)H;
    *(uint2*)(lo + 4 * (size_t)i) = *(uint2*)L;
}

// W [K][N] row-major -> hi/lo [N][K]  (tiled smem transpose)
__global__ void tsplit(const float* __restrict__ w, __nv_bfloat16* __restrict__ hi,
                       __nv_bfloat16* __restrict__ lo, int K, int N)
{
    __shared__ float t[32][33];
    const int k0 = blockIdx.y << 5, n0 = blockIdx.x << 5;
    const int tx = threadIdx.x, ty = threadIdx.y;   // 32 x 8
#pragma unroll
    for (int i = 0; i < 4; i++)
        t[ty + 8 * i][tx] = w[(size_t)(k0 + ty + 8 * i) * N + n0 + tx];
    __syncthreads();
#pragma unroll
    for (int i = 0; i < 4; i++) {
        float a = t[tx][ty + 8 * i];
        __nv_bfloat16 h = __float2bfloat16(a);
        size_t o = (size_t)(n0 + ty + 8 * i) * K + k0 + tx;
        hi[o] = h;
        lo[o] = __float2bfloat16(a - __bfloat162float(h));
    }
}

// ---------------------------------------------------------------------------
// bf16x3 GEMM via mma.sync (HMMA):  C[M,N] = A[M,K] @ B^T[N,K]^T + bias[N]
// CTA tile 128x128, BK=32, 8 warps (2M x 4N), warp tile 64x32.
// Smem rows: 64B data + 16B pad (80B stride) -> ldmatrix conflict-free.
// Double-buffered cp.async stages of 40KB.
// ---------------------------------------------------------------------------
#define GST 40960   // Ah 10240 | Al 10240 | Bh 10240 | Bl 10240

__global__ __launch_bounds__(256, 1)
void gemm_mma(const __nv_bfloat16* __restrict__ Ahp, const __nv_bfloat16* __restrict__ Alp,
              const __nv_bfloat16* __restrict__ Bhp, const __nv_bfloat16* __restrict__ Blp,
              const float* __restrict__ bias, float* __restrict__ C,
              int M, int N, int K)
{
    extern __shared__ __align__(16) char smem[];
    const int tid = threadIdx.x, lane = tid & 31, warp = tid >> 5;
    const int wm = warp & 1, wn = warp >> 1;
    const int mBase = blockIdx.y * 128, nBase = blockIdx.x * 128;
    u32 sb = (u32)__cvta_generic_to_shared(smem);

    const int g = lane >> 3, rsel = lane & 7;
    // A frag addr: row = wm*64 + mi*16 + (g&1)*8 + rsel ; chunk = ks*2 + (g>>1)
    const u32 offA = (u32)((wm * 64 + (g & 1) * 8 + rsel) * 80 + (g >> 1) * 16);
    // B frag addr: row = wn*32 + nh*16 + (g>>1)*8 + rsel ; chunk = ks*2 + (g&1)
    const u32 offB = (u32)((wn * 32 + (g >> 1) * 8 + rsel) * 80 + (g & 1) * 16);

    float acc[4][4][4];
#pragma unroll
    for (int a = 0; a < 4; a++)
#pragma unroll
        for (int b = 0; b < 4; b++)
#pragma unroll
            for (int c = 0; c < 4; c++) acc[a][b][c] = 0.f;

    const int niter = K >> 5;

    auto load_stage = [&](int stage, int kc) {
        u32 st = sb + (u32)stage * GST;
#pragma unroll
        for (int i = 0; i < 2; i++) {
            int ch = i * 256 + tid;
            int row = ch >> 2, c = ch & 3;
            u32 d = st + (u32)(row * 80 + c * 16);
            size_t aoff = (size_t)(mBase + row) * K + kc * 32 + c * 8;
            size_t boff = (size_t)(nBase + row) * K + kc * 32 + c * 8;
            cpa16(d,         Ahp + aoff);
            cpa16(d + 10240, Alp + aoff);
            cpa16(d + 20480, Bhp + boff);
            cpa16(d + 30720, Blp + boff);
        }
        asm volatile("cp.async.commit_group;" ::: "memory");
    };

    load_stage(0, 0);
    for (int it = 0; it < niter; it++) {
        if (it + 1 < niter) {
            load_stage((it + 1) & 1, it + 1);
            asm volatile("cp.async.wait_group 1;" ::: "memory");
        } else {
            asm volatile("cp.async.wait_group 0;" ::: "memory");
        }
        __syncthreads();

        u32 st = sb + (u32)(it & 1) * GST;
#pragma unroll
        for (int ks = 0; ks < 2; ks++) {
            u32 ah[4][4], al[4][4], bh[4][2], bl[4][2];
#pragma unroll
            for (int mi = 0; mi < 4; mi++) {
                u32 a = st + offA + (u32)(mi * 16 * 80 + ks * 32);
                ldsm4(ah[mi], a);
                ldsm4(al[mi], a + 10240);
            }
#pragma unroll
            for (int nh = 0; nh < 2; nh++) {
                u32 b = st + 20480 + offB + (u32)(nh * 16 * 80 + ks * 32);
                u32 t[4];
                ldsm4(t, b);
                bh[2 * nh][0] = t[0]; bh[2 * nh][1] = t[1];
                bh[2 * nh + 1][0] = t[2]; bh[2 * nh + 1][1] = t[3];
                ldsm4(t, b + 10240);
                bl[2 * nh][0] = t[0]; bl[2 * nh][1] = t[1];
                bl[2 * nh + 1][0] = t[2]; bl[2 * nh + 1][1] = t[3];
            }
#pragma unroll
            for (int mi = 0; mi < 4; mi++)
#pragma unroll
                for (int ni = 0; ni < 4; ni++) {
                    mma_bf16(acc[mi][ni], ah[mi], bh[ni]);
                    mma_bf16(acc[mi][ni], ah[mi], bl[ni]);
                    mma_bf16(acc[mi][ni], al[mi], bh[ni]);
                }
        }
        __syncthreads();
    }

    // epilogue: c frag lane mapping (q = lane/4 row, 2*(lane%4) col)
    const int q = lane >> 2, t2 = (lane & 3) * 2;
#pragma unroll
    for (int mi = 0; mi < 4; mi++) {
        int r0 = mBase + wm * 64 + mi * 16 + q;
#pragma unroll
        for (int ni = 0; ni < 4; ni++) {
            int col = nBase + wn * 32 + ni * 8 + t2;
            float b0 = bias[col], b1 = bias[col + 1];
            *(float2*)&C[(size_t)r0 * N + col] =
                make_float2(acc[mi][ni][0] + b0, acc[mi][ni][1] + b1);
            *(float2*)&C[(size_t)(r0 + 8) * N + col] =
                make_float2(acc[mi][ni][2] + b0, acc[mi][ni][3] + b1);
        }
    }
}

// ---------------------------------------------------------------------------
// RoPE + scatter (coalesced via smem transpose):
// g_qkv [b*s][h*384+{q,k,v}] -> Q,K as [bh][d][s] (Q pre-scaled), V [bh][s][d]
// ---------------------------------------------------------------------------
__global__ __launch_bounds__(256)
void rope_scatter(const float* __restrict__ qkv, float* __restrict__ q,
                  float* __restrict__ k, float* __restrict__ v)
{
    __shared__ float sq[128][33];
    __shared__ float sk[128][33];
    const int s0 = blockIdx.x << 5;
    const int bh = blockIdx.y;
    const int b = bh >> 4, h = bh & 15;
    const int tid = threadIdx.x;

#pragma unroll
    for (int i = 0; i < 16; i++) {
        int idx = i * 256 + tid;
        int d = idx & 127, s = idx >> 7;
        const float* src = qkv + ((size_t)(b * SEQ + s0 + s)) * NQKV + h * 384;
        float qv = src[d], kv = src[128 + d];
        v[(size_t)bh * SEQ * 128 + (size_t)(s0 + s) * 128 + d] = src[256 + d];
        if (d < 32) {
            int fi = d & 15;
            float invf = expf(-(float)fi * (9.210340371976184f / 16.0f));
            float sn, cs;
            sincosf((float)(s0 + s) * invf, &sn, &cs);
            float q2 = (d < 16) ? -src[d + 16]       : src[d - 16];
            float k2 = (d < 16) ? -src[128 + d + 16] : src[128 + d - 16];
            qv = qv * cs + q2 * sn;
            kv = kv * cs + k2 * sn;
        }
        sq[d][s] = qv * 0.08838834764831843f;   // 1/sqrt(128)
        sk[d][s] = kv;
    }
    __syncthreads();
#pragma unroll
    for (int i = 0; i < 16; i++) {
        int idx = i * 256 + tid;
        int s = idx & 31, d = idx >> 5;
        size_t o = (size_t)bh * 128 * SEQ + (size_t)d * SEQ + s0 + s;
        q[o] = sq[d][s];
        k[o] = sk[d][s];
    }
}

// ---------------------------------------------------------------------------
// Flash attention, fp32 causal (unchanged from R8 pass).  BQ=BKV=64, D=128.
// ---------------------------------------------------------------------------
#define FL_SMEM_FLOATS (128*128 + 128*64 + 64*128 + 64*140)
#define FL_SMEM_BYTES  (FL_SMEM_FLOATS * 4)

__global__ __launch_bounds__(256)
void flash_kernel(const float* __restrict__ gq_all, const float* __restrict__ gk_all,
                  const float* __restrict__ gv_all, float* __restrict__ out)
{
    extern __shared__ __align__(16) float sm[];
    float* Qs2 = sm;               // [128][128]  dup over q
    float* Ks  = sm + 16384;       // [128][64]
    float* Vs  = sm + 24576;       // [64][128]
    float* Ps2 = sm + 32768;       // [64][140]   dup over k, padded

    const int tid = threadIdx.x;
    const int tx = tid & 15, ty = tid >> 4;
    const int qt = 31 - (int)blockIdx.x;
    const int bh = blockIdx.y;
    const int q0 = qt << 6;

    const float* gq = gq_all + (size_t)bh * 128 * SEQ;
    const float* gk = gk_all + (size_t)bh * 128 * SEQ;
    const float* gv = gv_all + (size_t)bh * SEQ * 128;

    {
        const int c = tx * 4;
#pragma unroll
        for (int p = 0; p < 8; p++) {
            int d = p * 16 + ty;
            float4 v = *(const float4*)&gq[(size_t)d * SEQ + q0 + c];
            *(float4*)&Qs2[d * 128 + 2 * c]     = make_float4(v.x, v.x, v.y, v.y);
            *(float4*)&Qs2[d * 128 + 2 * c + 4] = make_float4(v.z, v.z, v.w, v.w);
        }
    }

    u64 acc[4][4];
#pragma unroll
    for (int i = 0; i < 4; i++)
#pragma unroll
        for (int j = 0; j < 4; j++) acc[i][j] = 0ull;
    float mrun[4] = {-1e30f, -1e30f, -1e30f, -1e30f};
    float lrun[4] = {0.f, 0.f, 0.f, 0.f};

    for (int kt = 0; kt <= qt; kt++) {
        __syncthreads();
        {
            const int c = tx * 4;
#pragma unroll
            for (int p = 0; p < 8; p++) {
                int d = p * 16 + ty;
                *(float4*)&Ks[d * 64 + c] =
                    *(const float4*)&gk[(size_t)d * SEQ + kt * 64 + c];
            }
            const int r2 = tid >> 5, c2 = (tid & 31) * 4;
#pragma unroll
            for (int p = 0; p < 8; p++) {
                int row = p * 8 + r2;
                *(float4*)&Vs[row * 128 + c2] =
                    *(const float4*)&gv[(size_t)(kt * 64 + row) * 128 + c2];
            }
        }
        __syncthreads();

        u64 s2[4][2];
#pragma unroll
        for (int i = 0; i < 4; i++) { s2[i][0] = 0ull; s2[i][1] = 0ull; }
#pragma unroll 8
        for (int d = 0; d < 128; d++) {
            ulonglong2 a01 = *(const ulonglong2*)&Qs2[d * 128 + ty * 8];
            ulonglong2 a23 = *(const ulonglong2*)&Qs2[d * 128 + ty * 8 + 4];
            ulonglong2 bb  = *(const ulonglong2*)&Ks[d * 64 + tx * 4];
            ffma2(s2[0][0], a01.x, bb.x); ffma2(s2[0][1], a01.x, bb.y);
            ffma2(s2[1][0], a01.y, bb.x); ffma2(s2[1][1], a01.y, bb.y);
            ffma2(s2[2][0], a23.x, bb.x); ffma2(s2[2][1], a23.x, bb.y);
            ffma2(s2[3][0], a23.y, bb.x); ffma2(s2[3][1], a23.y, bb.y);
        }

        float s[4][4];
#pragma unroll
        for (int i = 0; i < 4; i++) {
            float2 u0 = unpack2(s2[i][0]), u1 = unpack2(s2[i][1]);
            s[i][0] = u0.x; s[i][1] = u0.y; s[i][2] = u1.x; s[i][3] = u1.y;
        }

        if (kt == qt) {
#pragma unroll
            for (int i = 0; i < 4; i++)
#pragma unroll
                for (int j = 0; j < 4; j++)
                    if (kt * 64 + tx * 4 + j > q0 + ty * 4 + i) s[i][j] = -1e30f;
        }

        float p[4][4], scale[4];
#pragma unroll
        for (int i = 0; i < 4; i++) {
            float m = fmaxf(fmaxf(s[i][0], s[i][1]), fmaxf(s[i][2], s[i][3]));
#pragma unroll
            for (int off = 8; off >= 1; off >>= 1)
                m = fmaxf(m, __shfl_xor_sync(0xffffffffu, m, off, 16));
            float mn = fmaxf(mrun[i], m);
            scale[i] = __expf(mrun[i] - mn);
            mrun[i] = mn;
            float l = 0.f;
#pragma unroll
            for (int j = 0; j < 4; j++) { p[i][j] = __expf(s[i][j] - mn); l += p[i][j]; }
#pragma unroll
            for (int off = 8; off >= 1; off >>= 1)
                l += __shfl_xor_sync(0xffffffffu, l, off, 16);
            lrun[i] = lrun[i] * scale[i] + l;
        }
#pragma unroll
        for (int i = 0; i < 4; i++) {
            u64 sd = pack2(scale[i], scale[i]);
            fmul2(acc[i][0], sd); fmul2(acc[i][1], sd);
            fmul2(acc[i][2], sd); fmul2(acc[i][3], sd);
        }

#pragma unroll
        for (int i = 0; i < 4; i++)
#pragma unroll
            for (int j = 0; j < 4; j++)
                *(u64*)&Ps2[(ty * 4 + i) * 140 + (tx * 4 + j) * 2] = pack2(p[i][j], p[i][j]);
        __syncthreads();

#pragma unroll 4
        for (int kk2 = 0; kk2 < 32; kk2++) {
            const int kk = kk2 * 2;
            ulonglong2 pv[4];
#pragma unroll
            for (int i = 0; i < 4; i++)
                pv[i] = *(const ulonglong2*)&Ps2[(ty * 4 + i) * 140 + kk2 * 4];
            ulonglong2 va = *(const ulonglong2*)&Vs[kk * 128 + tx * 4];
            ulonglong2 vb = *(const ulonglong2*)&Vs[kk * 128 + 64 + tx * 4];
            ulonglong2 vc = *(const ulonglong2*)&Vs[(kk + 1) * 128 + tx * 4];
            ulonglong2 vd = *(const ulonglong2*)&Vs[(kk + 1) * 128 + 64 + tx * 4];
#pragma unroll
            for (int i = 0; i < 4; i++) {
                ffma2(acc[i][0], pv[i].x, va.x); ffma2(acc[i][1], pv[i].x, va.y);
                ffma2(acc[i][2], pv[i].x, vb.x); ffma2(acc[i][3], pv[i].x, vb.y);
                ffma2(acc[i][0], pv[i].y, vc.x); ffma2(acc[i][1], pv[i].y, vc.y);
                ffma2(acc[i][2], pv[i].y, vd.x); ffma2(acc[i][3], pv[i].y, vd.y);
            }
        }
    }

    const int b = bh >> 4, h = bh & 15;
#pragma unroll
    for (int i = 0; i < 4; i++) {
        float inv = 1.0f / lrun[i];
        int q = q0 + ty * 4 + i;
        float* op = out + ((size_t)(b * SEQ + q)) * HID + h * 128;
        float2 f0 = unpack2(acc[i][0]), f1 = unpack2(acc[i][1]);
        float2 f2 = unpack2(acc[i][2]), f3 = unpack2(acc[i][3]);
        *(float4*)&op[tx * 4] =
            make_float4(f0.x * inv, f0.y * inv, f1.x * inv, f1.y * inv);
        *(float4*)&op[64 + tx * 4] =
            make_float4(f2.x * inv, f2.y * inv, f3.x * inv, f3.y * inv);
    }
}

// ---------------------------------------------------------------------------
extern "C" void kernel_launch(void* const* d_in, const int* in_sizes, int n_in,
                              void* d_out, int out_size)
{
    const float* hidden = (const float*)d_in[0];
    const float* qkvk = (const float*)d_in[2];
    const float* qkvb = (const float*)d_in[3];
    const float* outk = (const float*)d_in[4];
    const float* outb = (const float*)d_in[5];
    float* out = (float*)d_out;

    float *pqkv, *pq, *pk, *pv, *pattn;
    __nv_bfloat16 *pah, *pal, *pbh, *pbl;
    cudaGetSymbolAddress((void**)&pqkv,  g_qkv);
    cudaGetSymbolAddress((void**)&pq,    g_q);
    cudaGetSymbolAddress((void**)&pk,    g_k);
    cudaGetSymbolAddress((void**)&pv,    g_v);
    cudaGetSymbolAddress((void**)&pattn, g_attn);
    cudaGetSymbolAddress((void**)&pah,   g_ah);
    cudaGetSymbolAddress((void**)&pal,   g_al);
    cudaGetSymbolAddress((void**)&pbh,   g_bh);
    cudaGetSymbolAddress((void**)&pbl,   g_bl);

    cudaFuncSetAttribute((const void*)flash_kernel,
                         cudaFuncAttributeMaxDynamicSharedMemorySize, FL_SMEM_BYTES);
    cudaFuncSetAttribute((const void*)gemm_mma,
                         cudaFuncAttributeMaxDynamicSharedMemorySize, 2 * GST);

    // --- QKV projection: [4096,2048] @ [2048,6144] + bias (bf16x3 HMMA) ---
    split_rm<<<(4096 * 2048 / 4 + 255) / 256, 256>>>((const float4*)hidden, pah, pal, 4096 * 2048 / 4);
    tsplit<<<dim3(6144 / 32, 2048 / 32), dim3(32, 8)>>>(qkvk, pbh, pbl, 2048, 6144);
    gemm_mma<<<dim3(48, 32), 256, 2 * GST>>>(pah, pal, pbh, pbl, qkvb, pqkv, 4096, 6144, 2048);

    // --- RoPE + scatter ---
    rope_scatter<<<dim3(SEQ / 32, 32), 256>>>(pqkv, pq, pk, pv);

    // --- causal flash attention ---
    flash_kernel<<<dim3(32, 32), 256, FL_SMEM_BYTES>>>(pq, pk, pv, pattn);

    // --- output projection: [4096,2048] @ [2048,2048] + bias (bf16x3 HMMA) ---
    split_rm<<<(4096 * 2048 / 4 + 255) / 256, 256>>>((const float4*)pattn, pah, pal, 4096 * 2048 / 4);
    tsplit<<<dim3(2048 / 32, 2048 / 32), dim3(32, 8)>>>(outk, pbh, pbl, 2048, 2048);
    gemm_mma<<<dim3(16, 32), 256, 2 * GST>>>(pah, pal, pbh, pbl, outb, out, 4096, 2048, 2048);
}

// round 11
// speedup vs baseline: 2.6023x; 1.5347x over previous
#include <cuda_runtime.h>
#include <cuda_bf16.h>
#include <math.h>
#include <stdint.h>

#define SEQ    2048
#define NQKV   6144
#define HID    2048

typedef unsigned long long u64;
typedef unsigned int u32;

// ------------------------- scratch (device globals) -------------------------
__device__ float g_qkv [(size_t)2 * SEQ * NQKV];          // [b*s][6144]
__device__ __nv_bfloat16 g_qh[(size_t)32 * SEQ * 128];    // [bh][s][d]
__device__ __nv_bfloat16 g_ql[(size_t)32 * SEQ * 128];
__device__ __nv_bfloat16 g_kh[(size_t)32 * SEQ * 128];
__device__ __nv_bfloat16 g_kl[(size_t)32 * SEQ * 128];
__device__ __nv_bfloat16 g_vh[(size_t)32 * SEQ * 128];
__device__ __nv_bfloat16 g_vl[(size_t)32 * SEQ * 128];
__device__ __nv_bfloat16 g_ah[(size_t)4096 * 2048];       // A hi  [M][K]
__device__ __nv_bfloat16 g_al[(size_t)4096 * 2048];       // A lo
__device__ __nv_bfloat16 g_bh[(size_t)6144 * 2048];       // B^T hi [N][K]
__device__ __nv_bfloat16 g_bl[(size_t)6144 * 2048];       // B^T lo

// ------------------------- async / mma helpers (base PTX only) ---------------
__device__ __forceinline__ void cpa16(u32 dst, const void* src) {
    asm volatile("cp.async.cg.shared.global [%0], [%1], 16;" :: "r"(dst), "l"(src));
}
__device__ __forceinline__ void ldsm4(u32 r[4], u32 addr) {
    asm volatile("ldmatrix.sync.aligned.m8n8.x4.shared.b16 {%0,%1,%2,%3}, [%4];"
                 : "=r"(r[0]), "=r"(r[1]), "=r"(r[2]), "=r"(r[3]) : "r"(addr));
}
__device__ __forceinline__ void ldsm4t(u32 r[4], u32 addr) {
    asm volatile("ldmatrix.sync.aligned.m8n8.x4.trans.shared.b16 {%0,%1,%2,%3}, [%4];"
                 : "=r"(r[0]), "=r"(r[1]), "=r"(r[2]), "=r"(r[3]) : "r"(addr));
}
__device__ __forceinline__ void mma_bf16(float c[4], const u32 a[4], const u32 b[2]) {
    asm volatile("mma.sync.aligned.m16n8k16.row.col.f32.bf16.bf16.f32 "
                 "{%0,%1,%2,%3}, {%4,%5,%6,%7}, {%8,%9}, {%0,%1,%2,%3};"
                 : "+f"(c[0]), "+f"(c[1]), "+f"(c[2]), "+f"(c[3])
                 : "r"(a[0]), "r"(a[1]), "r"(a[2]), "r"(a[3]), "r"(b[0]), "r"(b[1]));
}

// fast exp on the FMA pipe (rel err ~2.4e-6 for x <= ~30)
__device__ __forceinline__ float fexp(float x) {
    float t = fmaxf(x, -80.f) * 1.4426950408889634f;
    float z = t + 12582912.f;
    int e = __float_as_int(z) - 0x4B400000;
    float f = t - (z - 12582912.f);
    float g = f * 0.6931471805599453f;
    float r = fmaf(g, 0.0083333333f, 0.0416666667f);
    r = fmaf(g, r, 0.16666667f);
    r = fmaf(g, r, 0.5f);
    r = fmaf(g, r, 1.0f);
    r = fmaf(g, r, 1.0f);
    return r * __int_as_float((e + 127) << 23);
}

// split two floats into packed bf16 hi-pair and lo-pair
__device__ __forceinline__ void split2(float a, float b, u32 &hi, u32 &lo) {
    __nv_bfloat162 h = __floats2bfloat162_rn(a, b);
    hi = *(u32*)&h;
    float ra = a - __bfloat162float(h.x);
    float rb = b - __bfloat162float(h.y);
    __nv_bfloat162 l = __floats2bfloat162_rn(ra, rb);
    lo = *(u32*)&l;
}

// ---------------------------------------------------------------------------
// Split kernels: fp32 -> (bf16 hi, bf16 lo)
// ---------------------------------------------------------------------------
__global__ void split_rm(const float4* __restrict__ x, __nv_bfloat16* __restrict__ hi,
                         __nv_bfloat16* __restrict__ lo, int n4)
{
    int i = blockIdx.x * 256 + threadIdx.x;
    if (i >= n4) return;
    float4 v = x[i];
    float a[4] = {v.x, v.y, v.z, v.w};
    __nv_bfloat16 H[4], L[4];
#pragma unroll
    for (int j = 0; j < 4; j++) {
        H[j] = __float2bfloat16(a[j]);
        L[j] = __float2bfloat16(a[j] - __bfloat162float(H[j]));
    }
    *(uint2*)(hi + 4 * (size_t)i) = *(uint2*)H;
    *(uint2*)(lo + 4 * (size_t)i) = *(uint2*)L;
}

// W [K][N] row-major -> hi/lo [N][K]  (tiled smem transpose)
__global__ void tsplit(const float* __restrict__ w, __nv_bfloat16* __restrict__ hi,
                       __nv_bfloat16* __restrict__ lo, int K, int N)
{
    __shared__ float t[32][33];
    const int k0 = blockIdx.y << 5, n0 = blockIdx.x << 5;
    const int tx = threadIdx.x, ty = threadIdx.y;   // 32 x 8
#pragma unroll
    for (int i = 0; i < 4; i++)
        t[ty + 8 * i][tx] = w[(size_t)(k0 + ty + 8 * i) * N + n0 + tx];
    __syncthreads();
#pragma unroll
    for (int i = 0; i < 4; i++) {
        float a = t[tx][ty + 8 * i];
        __nv_bfloat16 h = __float2bfloat16(a);
        size_t o = (size_t)(n0 + ty + 8 * i) * K + k0 + tx;
        hi[o] = h;
        lo[o] = __float2bfloat16(a - __bfloat162float(h));
    }
}

// ---------------------------------------------------------------------------
// bf16x3 GEMM via mma.sync (HMMA):  C[M,N] = A[M,K] @ B^T[N,K]^T + bias[N]
// (unchanged from R10 — verified)
// ---------------------------------------------------------------------------
#define GST 40960   // Ah 10240 | Al 10240 | Bh 10240 | Bl 10240

__global__ __launch_bounds__(256, 1)
void gemm_mma(const __nv_bfloat16* __restrict__ Ahp, const __nv_bfloat16* __restrict__ Alp,
              const __nv_bfloat16* __restrict__ Bhp, const __nv_bfloat16* __restrict__ Blp,
              const float* __restrict__ bias, float* __restrict__ C,
              int M, int N, int K)
{
    extern __shared__ __align__(16) char smem[];
    const int tid = threadIdx.x, lane = tid & 31, warp = tid >> 5;
    const int wm = warp & 1, wn = warp >> 1;
    const int mBase = blockIdx.y * 128, nBase = blockIdx.x * 128;
    u32 sb = (u32)__cvta_generic_to_shared(smem);

    const int g = lane >> 3, rsel = lane & 7;
    const u32 offA = (u32)((wm * 64 + (g & 1) * 8 + rsel) * 80 + (g >> 1) * 16);
    const u32 offB = (u32)((wn * 32 + (g >> 1) * 8 + rsel) * 80 + (g & 1) * 16);

    float acc[4][4][4];
#pragma unroll
    for (int a = 0; a < 4; a++)
#pragma unroll
        for (int b = 0; b < 4; b++)
#pragma unroll
            for (int c = 0; c < 4; c++) acc[a][b][c] = 0.f;

    const int niter = K >> 5;

    auto load_stage = [&](int stage, int kc) {
        u32 st = sb + (u32)stage * GST;
#pragma unroll
        for (int i = 0; i < 2; i++) {
            int ch = i * 256 + tid;
            int row = ch >> 2, c = ch & 3;
            u32 d = st + (u32)(row * 80 + c * 16);
            size_t aoff = (size_t)(mBase + row) * K + kc * 32 + c * 8;
            size_t boff = (size_t)(nBase + row) * K + kc * 32 + c * 8;
            cpa16(d,         Ahp + aoff);
            cpa16(d + 10240, Alp + aoff);
            cpa16(d + 20480, Bhp + boff);
            cpa16(d + 30720, Blp + boff);
        }
        asm volatile("cp.async.commit_group;" ::: "memory");
    };

    load_stage(0, 0);
    for (int it = 0; it < niter; it++) {
        if (it + 1 < niter) {
            load_stage((it + 1) & 1, it + 1);
            asm volatile("cp.async.wait_group 1;" ::: "memory");
        } else {
            asm volatile("cp.async.wait_group 0;" ::: "memory");
        }
        __syncthreads();

        u32 st = sb + (u32)(it & 1) * GST;
#pragma unroll
        for (int ks = 0; ks < 2; ks++) {
            u32 ah[4][4], al[4][4], bh[4][2], bl[4][2];
#pragma unroll
            for (int mi = 0; mi < 4; mi++) {
                u32 a = st + offA + (u32)(mi * 16 * 80 + ks * 32);
                ldsm4(ah[mi], a);
                ldsm4(al[mi], a + 10240);
            }
#pragma unroll
            for (int nh = 0; nh < 2; nh++) {
                u32 b = st + 20480 + offB + (u32)(nh * 16 * 80 + ks * 32);
                u32 t[4];
                ldsm4(t, b);
                bh[2 * nh][0] = t[0]; bh[2 * nh][1] = t[1];
                bh[2 * nh + 1][0] = t[2]; bh[2 * nh + 1][1] = t[3];
                ldsm4(t, b + 10240);
                bl[2 * nh][0] = t[0]; bl[2 * nh][1] = t[1];
                bl[2 * nh + 1][0] = t[2]; bl[2 * nh + 1][1] = t[3];
            }
#pragma unroll
            for (int mi = 0; mi < 4; mi++)
#pragma unroll
                for (int ni = 0; ni < 4; ni++) {
                    mma_bf16(acc[mi][ni], ah[mi], bh[ni]);
                    mma_bf16(acc[mi][ni], ah[mi], bl[ni]);
                    mma_bf16(acc[mi][ni], al[mi], bh[ni]);
                }
        }
        __syncthreads();
    }

    const int q = lane >> 2, t2 = (lane & 3) * 2;
#pragma unroll
    for (int mi = 0; mi < 4; mi++) {
        int r0 = mBase + wm * 64 + mi * 16 + q;
#pragma unroll
        for (int ni = 0; ni < 4; ni++) {
            int col = nBase + wn * 32 + ni * 8 + t2;
            float b0 = bias[col], b1 = bias[col + 1];
            *(float2*)&C[(size_t)r0 * N + col] =
                make_float2(acc[mi][ni][0] + b0, acc[mi][ni][1] + b1);
            *(float2*)&C[(size_t)(r0 + 8) * N + col] =
                make_float2(acc[mi][ni][2] + b0, acc[mi][ni][3] + b1);
        }
    }
}

// ---------------------------------------------------------------------------
// RoPE + bf16 hi/lo split:  g_qkv [b*s][h*384+{q,k,v}] ->
//   qh/ql, kh/kl, vh/vl as [bh][s][128] bf16.  Q pre-scaled by 1/sqrt(128).
// ---------------------------------------------------------------------------
__global__ __launch_bounds__(256)
void rope_split(const float* __restrict__ qkv,
                __nv_bfloat16* __restrict__ qh, __nv_bfloat16* __restrict__ ql,
                __nv_bfloat16* __restrict__ kh, __nv_bfloat16* __restrict__ kl,
                __nv_bfloat16* __restrict__ vh, __nv_bfloat16* __restrict__ vl)
{
    int idx = blockIdx.x * 256 + threadIdx.x;     // over 32*2048*128
    int d = idx & 127;
    int s = (idx >> 7) & 2047;
    int bh = idx >> 18;
    int b = bh >> 4, h = bh & 15;

    const float* src = qkv + ((size_t)(b * SEQ + s)) * NQKV + h * 384;
    float qv = src[d], kv = src[128 + d], vv = src[256 + d];

    if (d < 32) {
        int fi = d & 15;
        float invf = expf(-(float)fi * (9.210340371976184f / 16.0f));
        float sn, cs;
        sincosf((float)s * invf, &sn, &cs);
        float q2 = (d < 16) ? -src[d + 16]       : src[d - 16];
        float k2 = (d < 16) ? -src[128 + d + 16] : src[128 + d - 16];
        qv = qv * cs + q2 * sn;
        kv = kv * cs + k2 * sn;
    }
    qv *= 0.08838834764831843f;   // 1/sqrt(128)

    size_t o = (size_t)bh * SEQ * 128 + (size_t)s * 128 + d;
    __nv_bfloat16 x;
    x = __float2bfloat16(qv); qh[o] = x; ql[o] = __float2bfloat16(qv - __bfloat162float(x));
    x = __float2bfloat16(kv); kh[o] = x; kl[o] = __float2bfloat16(kv - __bfloat162float(x));
    x = __float2bfloat16(vv); vh[o] = x; vl[o] = __float2bfloat16(vv - __bfloat162float(x));
}

// ---------------------------------------------------------------------------
// Flash attention via mma.sync, bf16x3, causal, no-max softmax.
// BQ=128 (8 warps x 16 rows), BKV=64, D=128.
// Smem: Q hi/lo resident (69632B) + 2 KV stages (69632B each) = 208896B.
// Row stride 272B -> ldmatrix conflict-free.  Output written pre-split
// into g_ah/g_al (fused with out-proj A-operand prep).
// ---------------------------------------------------------------------------
#define FSTG 69632

__global__ __launch_bounds__(256, 1)
void flash_mma(const __nv_bfloat16* __restrict__ qhp, const __nv_bfloat16* __restrict__ qlp,
               const __nv_bfloat16* __restrict__ khp, const __nv_bfloat16* __restrict__ klp,
               const __nv_bfloat16* __restrict__ vhp, const __nv_bfloat16* __restrict__ vlp,
               __nv_bfloat16* __restrict__ oh, __nv_bfloat16* __restrict__ ol)
{
    extern __shared__ __align__(16) char smem[];
    const int tid = threadIdx.x, lane = tid & 31, warp = tid >> 5;
    const int qi = 15 - (int)blockIdx.x;        // heavy q-tiles first
    const int bh = blockIdx.y;
    const int q0 = qi << 7;
    const int nkv = 2 * qi + 2;
    u32 sb = (u32)__cvta_generic_to_shared(smem);

    const int g = lane >> 3, rsel = lane & 7;
    const size_t base = (size_t)bh * SEQ * 128;

    // ---- issue Q loads (resident region: Qh @0, Ql @34816) ----
#pragma unroll
    for (int i = 0; i < 8; i++) {
        int idx = i * 256 + tid;                 // 0..2047
        int row = idx >> 4, c = idx & 15;
        u32 d = sb + (u32)(row * 272 + c * 16);
        size_t s = base + (size_t)(q0 + row) * 128 + c * 8;
        cpa16(d,         qhp + s);
        cpa16(d + 34816, qlp + s);
    }
    asm volatile("cp.async.commit_group;" ::: "memory");

    auto load_kv = [&](int kt) {
        u32 st = sb + (u32)(FSTG + (kt & 1) * FSTG);
        const size_t rb = base + (size_t)(kt * 64) * 128;
#pragma unroll
        for (int i = 0; i < 4; i++) {
            int idx = i * 256 + tid;             // 0..1023
            int row = idx >> 4, c = idx & 15;
            u32 d = st + (u32)(row * 272 + c * 16);
            size_t s = rb + (size_t)row * 128 + c * 8;
            cpa16(d,         khp + s);
            cpa16(d + 17408, klp + s);
            cpa16(d + 34816, vhp + s);
            cpa16(d + 52224, vlp + s);
        }
        asm volatile("cp.async.commit_group;" ::: "memory");
    };

    load_kv(0);

    float oacc[16][4];
#pragma unroll
    for (int i = 0; i < 16; i++)
#pragma unroll
        for (int j = 0; j < 4; j++) oacc[i][j] = 0.f;
    float lsum0 = 0.f, lsum1 = 0.f;

    const u32 qoff = sb + (u32)((warp * 16 + (g & 1) * 8 + rsel) * 272 + (g >> 1) * 16);
    const int rowq = warp * 16 + (lane >> 2);        // local q row (of pair)

    for (int kt = 0; kt < nkv; kt++) {
        if (kt + 1 < nkv) {
            load_kv(kt + 1);
            asm volatile("cp.async.wait_group 1;" ::: "memory");
        } else {
            asm volatile("cp.async.wait_group 0;" ::: "memory");
        }
        __syncthreads();
        u32 st = sb + (u32)(FSTG + (kt & 1) * FSTG);

        // ---- S = Q K^T  (bf16x3) ----
        float sacc[8][4];
#pragma unroll
        for (int i = 0; i < 8; i++)
#pragma unroll
            for (int j = 0; j < 4; j++) sacc[i][j] = 0.f;

        const u32 kb = st + (u32)(((g >> 1) * 8 + rsel) * 272 + (g & 1) * 16);
#pragma unroll
        for (int ks = 0; ks < 8; ks++) {
            u32 ah4[4], al4[4];
            ldsm4(ah4, qoff + ks * 32);
            ldsm4(al4, qoff + 34816 + ks * 32);
            u32 tb[4][4], tl[4][4];
#pragma unroll
            for (int ng = 0; ng < 4; ng++) {
                ldsm4(tb[ng], kb + ng * (16 * 272) + ks * 32);
                ldsm4(tl[ng], kb + 17408 + ng * (16 * 272) + ks * 32);
            }
#pragma unroll
            for (int ng = 0; ng < 4; ng++) {
                mma_bf16(sacc[2 * ng],     ah4, tb[ng]);
                mma_bf16(sacc[2 * ng],     al4, tb[ng]);
                mma_bf16(sacc[2 * ng],     ah4, tl[ng]);
                mma_bf16(sacc[2 * ng + 1], ah4, tb[ng] + 2);
                mma_bf16(sacc[2 * ng + 1], al4, tb[ng] + 2);
                mma_bf16(sacc[2 * ng + 1], ah4, tl[ng] + 2);
            }
        }

        // ---- softmax numerator (no max-subtraction; scores are O(1)) ----
        const bool diag = (kt >= 2 * qi);
        const int row0 = q0 + rowq;
        const int colb = kt * 64 + 2 * (lane & 3);
        u32 pah[4][4], pal[4][4];
#pragma unroll
        for (int ni = 0; ni < 8; ni++) {
            int c0 = colb + ni * 8;
            float p0, p1, p2, p3;
            if (diag) {
                p0 = (c0     <= row0    ) ? fexp(sacc[ni][0]) : 0.f;
                p1 = (c0 + 1 <= row0    ) ? fexp(sacc[ni][1]) : 0.f;
                p2 = (c0     <= row0 + 8) ? fexp(sacc[ni][2]) : 0.f;
                p3 = (c0 + 1 <= row0 + 8) ? fexp(sacc[ni][3]) : 0.f;
            } else {
                p0 = fexp(sacc[ni][0]); p1 = fexp(sacc[ni][1]);
                p2 = fexp(sacc[ni][2]); p3 = fexp(sacc[ni][3]);
            }
            lsum0 += p0 + p1;
            lsum1 += p2 + p3;
            int kt2 = ni >> 1, j = (ni & 1) * 2;
            split2(p0, p1, pah[kt2][j],     pal[kt2][j]);
            split2(p2, p3, pah[kt2][j + 1], pal[kt2][j + 1]);
        }

        // ---- O += P V  (bf16x3, V via trans ldmatrix) ----
        const u32 vb = st + 34816 + (u32)(((g & 1) * 8 + rsel) * 272 + (g >> 1) * 16);
#pragma unroll
        for (int kt2 = 0; kt2 < 4; kt2++) {
#pragma unroll
            for (int dg = 0; dg < 8; dg++) {
                u32 th[4], tl2[4];
                ldsm4t(th,  vb + kt2 * (16 * 272) + dg * 32);
                ldsm4t(tl2, vb + 17408 + kt2 * (16 * 272) + dg * 32);
                mma_bf16(oacc[2 * dg],     pah[kt2], th);
                mma_bf16(oacc[2 * dg],     pal[kt2], th);
                mma_bf16(oacc[2 * dg],     pah[kt2], tl2);
                mma_bf16(oacc[2 * dg + 1], pah[kt2], th + 2);
                mma_bf16(oacc[2 * dg + 1], pal[kt2], th + 2);
                mma_bf16(oacc[2 * dg + 1], pah[kt2], tl2 + 2);
            }
        }
        __syncthreads();
    }

    // ---- normalize + pre-split store into g_ah/g_al ----
    lsum0 += __shfl_xor_sync(0xffffffffu, lsum0, 1);
    lsum0 += __shfl_xor_sync(0xffffffffu, lsum0, 2);
    lsum1 += __shfl_xor_sync(0xffffffffu, lsum1, 1);
    lsum1 += __shfl_xor_sync(0xffffffffu, lsum1, 2);
    float inv0 = 1.f / lsum0, inv1 = 1.f / lsum1;

    const int b = bh >> 4, h = bh & 15;
    const int r0 = q0 + rowq;
    size_t obase0 = ((size_t)(b * SEQ + r0)) * HID + h * 128;
    size_t obase1 = obase0 + (size_t)8 * HID;
#pragma unroll
    for (int dt = 0; dt < 16; dt++) {
        int col = dt * 8 + 2 * (lane & 3);
        u32 hi0, lo0, hi1, lo1;
        split2(oacc[dt][0] * inv0, oacc[dt][1] * inv0, hi0, lo0);
        split2(oacc[dt][2] * inv1, oacc[dt][3] * inv1, hi1, lo1);
        *(u32*)(oh + obase0 + col) = hi0;
        *(u32*)(ol + obase0 + col) = lo0;
        *(u32*)(oh + obase1 + col) = hi1;
        *(u32*)(ol + obase1 + col) = lo1;
    }
}

// ---------------------------------------------------------------------------
extern "C" void kernel_launch(void* const* d_in, const int* in_sizes, int n_in,
                              void* d_out, int out_size)
{
    const float* hidden = (const float*)d_in[0];
    const float* qkvk = (const float*)d_in[2];
    const float* qkvb = (const float*)d_in[3];
    const float* outk = (const float*)d_in[4];
    const float* outb = (const float*)d_in[5];
    float* out = (float*)d_out;

    float* pqkv;
    __nv_bfloat16 *pqh, *pql, *pkh, *pkl, *pvh, *pvl, *pah, *pal, *pbh, *pbl;
    cudaGetSymbolAddress((void**)&pqkv, g_qkv);
    cudaGetSymbolAddress((void**)&pqh,  g_qh);
    cudaGetSymbolAddress((void**)&pql,  g_ql);
    cudaGetSymbolAddress((void**)&pkh,  g_kh);
    cudaGetSymbolAddress((void**)&pkl,  g_kl);
    cudaGetSymbolAddress((void**)&pvh,  g_vh);
    cudaGetSymbolAddress((void**)&pvl,  g_vl);
    cudaGetSymbolAddress((void**)&pah,  g_ah);
    cudaGetSymbolAddress((void**)&pal,  g_al);
    cudaGetSymbolAddress((void**)&pbh,  g_bh);
    cudaGetSymbolAddress((void**)&pbl,  g_bl);

    cudaFuncSetAttribute((const void*)gemm_mma,
                         cudaFuncAttributeMaxDynamicSharedMemorySize, 2 * GST);
    cudaFuncSetAttribute((const void*)flash_mma,
                         cudaFuncAttributeMaxDynamicSharedMemorySize, 3 * FSTG);

    // --- QKV projection: [4096,2048] @ [2048,6144] + bias ---
    split_rm<<<(4096 * 2048 / 4 + 255) / 256, 256>>>((const float4*)hidden, pah, pal, 4096 * 2048 / 4);
    tsplit<<<dim3(6144 / 32, 2048 / 32), dim3(32, 8)>>>(qkvk, pbh, pbl, 2048, 6144);
    gemm_mma<<<dim3(48, 32), 256, 2 * GST>>>(pah, pal, pbh, pbl, qkvb, pqkv, 4096, 6144, 2048);

    // --- RoPE + hi/lo split ---
    rope_split<<<32 * SEQ * 128 / 256, 256>>>(pqkv, pqh, pql, pkh, pkl, pvh, pvl);

    // --- causal flash attention (HMMA), writes pre-split A for out-proj ---
    flash_mma<<<dim3(16, 32), 256, 3 * FSTG>>>(pqh, pql, pkh, pkl, pvh, pvl, pah, pal);

    // --- output projection: [4096,2048] @ [2048,2048] + bias ---
    tsplit<<<dim3(2048 / 32, 2048 / 32), dim3(32, 8)>>>(outk, pbh, pbl, 2048, 2048);
    gemm_mma<<<dim3(16, 32), 256, 2 * GST>>>(pah, pal, pbh, pbl, outb, out, 4096, 2048, 2048);
}

// round 12
// speedup vs baseline: 2.6239x; 1.0083x over previous
#include <cuda_runtime.h>
#include <cuda_bf16.h>
#include <math.h>
#include <stdint.h>

#define SEQ    2048
#define NQKV   6144
#define HID    2048

typedef unsigned long long u64;
typedef unsigned int u32;

// ------------------------- scratch (device globals) -------------------------
__device__ float g_qkv [(size_t)2 * SEQ * NQKV];          // [b*s][6144]
__device__ __nv_bfloat16 g_qh[(size_t)32 * SEQ * 128];    // [bh][s][d]
__device__ __nv_bfloat16 g_ql[(size_t)32 * SEQ * 128];
__device__ __nv_bfloat16 g_kh[(size_t)32 * SEQ * 128];
__device__ __nv_bfloat16 g_kl[(size_t)32 * SEQ * 128];
__device__ __nv_bfloat16 g_vh[(size_t)32 * SEQ * 128];
__device__ __nv_bfloat16 g_vl[(size_t)32 * SEQ * 128];
__device__ __nv_bfloat16 g_ah[(size_t)4096 * 2048];       // A hi  [M][K]
__device__ __nv_bfloat16 g_al[(size_t)4096 * 2048];       // A lo
__device__ __nv_bfloat16 g_bh[(size_t)6144 * 2048];       // B^T hi [N][K]
__device__ __nv_bfloat16 g_bl[(size_t)6144 * 2048];       // B^T lo

// ------------------------- async / mma helpers (base PTX only) ---------------
__device__ __forceinline__ void cpa16(u32 dst, const void* src) {
    asm volatile("cp.async.cg.shared.global [%0], [%1], 16;" :: "r"(dst), "l"(src));
}
__device__ __forceinline__ void ldsm4(u32 r[4], u32 addr) {
    asm volatile("ldmatrix.sync.aligned.m8n8.x4.shared.b16 {%0,%1,%2,%3}, [%4];"
                 : "=r"(r[0]), "=r"(r[1]), "=r"(r[2]), "=r"(r[3]) : "r"(addr));
}
__device__ __forceinline__ void ldsm4t(u32 r[4], u32 addr) {
    asm volatile("ldmatrix.sync.aligned.m8n8.x4.trans.shared.b16 {%0,%1,%2,%3}, [%4];"
                 : "=r"(r[0]), "=r"(r[1]), "=r"(r[2]), "=r"(r[3]) : "r"(addr));
}
__device__ __forceinline__ void mma_bf16(float c[4], const u32 a[4], const u32 b[2]) {
    asm volatile("mma.sync.aligned.m16n8k16.row.col.f32.bf16.bf16.f32 "
                 "{%0,%1,%2,%3}, {%4,%5,%6,%7}, {%8,%9}, {%0,%1,%2,%3};"
                 : "+f"(c[0]), "+f"(c[1]), "+f"(c[2]), "+f"(c[3])
                 : "r"(a[0]), "r"(a[1]), "r"(a[2]), "r"(a[3]), "r"(b[0]), "r"(b[1]));
}

// fast exp on the FMA pipe (rel err ~2.4e-6)
__device__ __forceinline__ float fexp(float x) {
    float t = fmaxf(x, -80.f) * 1.4426950408889634f;
    float z = t + 12582912.f;
    int e = __float_as_int(z) - 0x4B400000;
    float f = t - (z - 12582912.f);
    float g = f * 0.6931471805599453f;
    float r = fmaf(g, 0.0083333333f, 0.0416666667f);
    r = fmaf(g, r, 0.16666667f);
    r = fmaf(g, r, 0.5f);
    r = fmaf(g, r, 1.0f);
    r = fmaf(g, r, 1.0f);
    return r * __int_as_float((e + 127) << 23);
}

// split two floats into packed bf16 hi-pair and lo-pair
__device__ __forceinline__ void split2(float a, float b, u32 &hi, u32 &lo) {
    __nv_bfloat162 h = __floats2bfloat162_rn(a, b);
    hi = *(u32*)&h;
    float ra = a - __bfloat162float(h.x);
    float rb = b - __bfloat162float(h.y);
    __nv_bfloat162 l = __floats2bfloat162_rn(ra, rb);
    lo = *(u32*)&l;
}

// ---------------------------------------------------------------------------
// Split kernels: fp32 -> (bf16 hi, bf16 lo)
// ---------------------------------------------------------------------------
__global__ void split_rm(const float4* __restrict__ x, __nv_bfloat16* __restrict__ hi,
                         __nv_bfloat16* __restrict__ lo, int n4)
{
    int i = blockIdx.x * 256 + threadIdx.x;
    if (i >= n4) return;
    float4 v = x[i];
    float a[4] = {v.x, v.y, v.z, v.w};
    __nv_bfloat16 H[4], L[4];
#pragma unroll
    for (int j = 0; j < 4; j++) {
        H[j] = __float2bfloat16(a[j]);
        L[j] = __float2bfloat16(a[j] - __bfloat162float(H[j]));
    }
    *(uint2*)(hi + 4 * (size_t)i) = *(uint2*)H;
    *(uint2*)(lo + 4 * (size_t)i) = *(uint2*)L;
}

// W [K][N] row-major -> hi/lo [N][K]  (tiled smem transpose)
__global__ void tsplit(const float* __restrict__ w, __nv_bfloat16* __restrict__ hi,
                       __nv_bfloat16* __restrict__ lo, int K, int N)
{
    __shared__ float t[32][33];
    const int k0 = blockIdx.y << 5, n0 = blockIdx.x << 5;
    const int tx = threadIdx.x, ty = threadIdx.y;   // 32 x 8
#pragma unroll
    for (int i = 0; i < 4; i++)
        t[ty + 8 * i][tx] = w[(size_t)(k0 + ty + 8 * i) * N + n0 + tx];
    __syncthreads();
#pragma unroll
    for (int i = 0; i < 4; i++) {
        float a = t[tx][ty + 8 * i];
        __nv_bfloat16 h = __float2bfloat16(a);
        size_t o = (size_t)(n0 + ty + 8 * i) * K + k0 + tx;
        hi[o] = h;
        lo[o] = __float2bfloat16(a - __bfloat162float(h));
    }
}

// ---------------------------------------------------------------------------
// bf16x3 GEMM via mma.sync (HMMA):  C[M,N] = A[M,K] @ B^T[N,K]^T + bias[N]
// 128x128 tile, BK=32, 8 warps (2M x 4N).  3-stage cp.async ring, one
// __syncthreads per iter, product-major MMA ordering (16 independent accs
// between accumulator reuse).
// ---------------------------------------------------------------------------
#define GST 40960   // Ah 10240 | Al 10240 | Bh 10240 | Bl 10240

__global__ __launch_bounds__(256, 1)
void gemm_mma(const __nv_bfloat16* __restrict__ Ahp, const __nv_bfloat16* __restrict__ Alp,
              const __nv_bfloat16* __restrict__ Bhp, const __nv_bfloat16* __restrict__ Blp,
              const float* __restrict__ bias, float* __restrict__ C,
              int M, int N, int K)
{
    extern __shared__ __align__(16) char smem[];
    const int tid = threadIdx.x, lane = tid & 31, warp = tid >> 5;
    const int wm = warp & 1, wn = warp >> 1;
    const int mBase = blockIdx.y * 128, nBase = blockIdx.x * 128;
    u32 sb = (u32)__cvta_generic_to_shared(smem);

    const int g = lane >> 3, rsel = lane & 7;
    const u32 offA = (u32)((wm * 64 + (g & 1) * 8 + rsel) * 80 + (g >> 1) * 16);
    const u32 offB = (u32)((wn * 32 + (g >> 1) * 8 + rsel) * 80 + (g & 1) * 16);

    float acc[4][4][4];
#pragma unroll
    for (int a = 0; a < 4; a++)
#pragma unroll
        for (int b = 0; b < 4; b++)
#pragma unroll
            for (int c = 0; c < 4; c++) acc[a][b][c] = 0.f;

    const int niter = K >> 5;

    auto load_stage = [&](int stage, int kc) {
        u32 st = sb + (u32)stage * GST;
#pragma unroll
        for (int i = 0; i < 2; i++) {
            int ch = i * 256 + tid;
            int row = ch >> 2, c = ch & 3;
            u32 d = st + (u32)(row * 80 + c * 16);
            size_t aoff = (size_t)(mBase + row) * K + kc * 32 + c * 8;
            size_t boff = (size_t)(nBase + row) * K + kc * 32 + c * 8;
            cpa16(d,         Ahp + aoff);
            cpa16(d + 10240, Alp + aoff);
            cpa16(d + 20480, Bhp + boff);
            cpa16(d + 30720, Blp + boff);
        }
        asm volatile("cp.async.commit_group;" ::: "memory");
    };

    load_stage(0, 0);
    load_stage(1, 1);

    for (int it = 0; it < niter; it++) {
        if (it + 1 < niter) {
            asm volatile("cp.async.wait_group 1;" ::: "memory");
        } else {
            asm volatile("cp.async.wait_group 0;" ::: "memory");
        }
        __syncthreads();
        if (it + 2 < niter) load_stage((it + 2) % 3, it + 2);

        u32 st = sb + (u32)(it % 3) * GST;
#pragma unroll
        for (int ks = 0; ks < 2; ks++) {
            u32 ah[4][4], al[4][4], bh[4][2], bl[4][2];
#pragma unroll
            for (int mi = 0; mi < 4; mi++) {
                u32 a = st + offA + (u32)(mi * 16 * 80 + ks * 32);
                ldsm4(ah[mi], a);
                ldsm4(al[mi], a + 10240);
            }
#pragma unroll
            for (int nh = 0; nh < 2; nh++) {
                u32 b = st + 20480 + offB + (u32)(nh * 16 * 80 + ks * 32);
                u32 t[4];
                ldsm4(t, b);
                bh[2 * nh][0] = t[0]; bh[2 * nh][1] = t[1];
                bh[2 * nh + 1][0] = t[2]; bh[2 * nh + 1][1] = t[3];
                ldsm4(t, b + 10240);
                bl[2 * nh][0] = t[0]; bl[2 * nh][1] = t[1];
                bl[2 * nh + 1][0] = t[2]; bl[2 * nh + 1][1] = t[3];
            }
            // product-major: all 16 accs between reuses
#pragma unroll
            for (int mi = 0; mi < 4; mi++)
#pragma unroll
                for (int ni = 0; ni < 4; ni++)
                    mma_bf16(acc[mi][ni], ah[mi], bh[ni]);
#pragma unroll
            for (int mi = 0; mi < 4; mi++)
#pragma unroll
                for (int ni = 0; ni < 4; ni++)
                    mma_bf16(acc[mi][ni], ah[mi], bl[ni]);
#pragma unroll
            for (int mi = 0; mi < 4; mi++)
#pragma unroll
                for (int ni = 0; ni < 4; ni++)
                    mma_bf16(acc[mi][ni], al[mi], bh[ni]);
        }
    }

    __syncthreads();
    const int q = lane >> 2, t2 = (lane & 3) * 2;
#pragma unroll
    for (int mi = 0; mi < 4; mi++) {
        int r0 = mBase + wm * 64 + mi * 16 + q;
#pragma unroll
        for (int ni = 0; ni < 4; ni++) {
            int col = nBase + wn * 32 + ni * 8 + t2;
            float b0 = bias[col], b1 = bias[col + 1];
            *(float2*)&C[(size_t)r0 * N + col] =
                make_float2(acc[mi][ni][0] + b0, acc[mi][ni][1] + b1);
            *(float2*)&C[(size_t)(r0 + 8) * N + col] =
                make_float2(acc[mi][ni][2] + b0, acc[mi][ni][3] + b1);
        }
    }
}

// ---------------------------------------------------------------------------
// RoPE + bf16 hi/lo split (unchanged)
// ---------------------------------------------------------------------------
__global__ __launch_bounds__(256)
void rope_split(const float* __restrict__ qkv,
                __nv_bfloat16* __restrict__ qh, __nv_bfloat16* __restrict__ ql,
                __nv_bfloat16* __restrict__ kh, __nv_bfloat16* __restrict__ kl,
                __nv_bfloat16* __restrict__ vh, __nv_bfloat16* __restrict__ vl)
{
    int idx = blockIdx.x * 256 + threadIdx.x;     // over 32*2048*128
    int d = idx & 127;
    int s = (idx >> 7) & 2047;
    int bh = idx >> 18;
    int b = bh >> 4, h = bh & 15;

    const float* src = qkv + ((size_t)(b * SEQ + s)) * NQKV + h * 384;
    float qv = src[d], kv = src[128 + d], vv = src[256 + d];

    if (d < 32) {
        int fi = d & 15;
        float invf = expf(-(float)fi * (9.210340371976184f / 16.0f));
        float sn, cs;
        sincosf((float)s * invf, &sn, &cs);
        float q2 = (d < 16) ? -src[d + 16]       : src[d - 16];
        float k2 = (d < 16) ? -src[128 + d + 16] : src[128 + d - 16];
        qv = qv * cs + q2 * sn;
        kv = kv * cs + k2 * sn;
    }
    qv *= 0.08838834764831843f;   // 1/sqrt(128)

    size_t o = (size_t)bh * SEQ * 128 + (size_t)s * 128 + d;
    __nv_bfloat16 x;
    x = __float2bfloat16(qv); qh[o] = x; ql[o] = __float2bfloat16(qv - __bfloat162float(x));
    x = __float2bfloat16(kv); kh[o] = x; kl[o] = __float2bfloat16(kv - __bfloat162float(x));
    x = __float2bfloat16(vv); vh[o] = x; vl[o] = __float2bfloat16(vv - __bfloat162float(x));
}

// ---------------------------------------------------------------------------
// Flash attention via mma.sync, bf16x3, causal, no-max softmax.
// BQ=128 (8 warps x 16 rows), BKV=64, D=128.  Single __syncthreads per kv
// step; KV(kt+1) issued right after the sync; product-major MMA ordering.
// Output written pre-split into g_ah/g_al.
// ---------------------------------------------------------------------------
#define FSTG 69632

__global__ __launch_bounds__(256, 1)
void flash_mma(const __nv_bfloat16* __restrict__ qhp, const __nv_bfloat16* __restrict__ qlp,
               const __nv_bfloat16* __restrict__ khp, const __nv_bfloat16* __restrict__ klp,
               const __nv_bfloat16* __restrict__ vhp, const __nv_bfloat16* __restrict__ vlp,
               __nv_bfloat16* __restrict__ oh, __nv_bfloat16* __restrict__ ol)
{
    extern __shared__ __align__(16) char smem[];
    const int tid = threadIdx.x, lane = tid & 31, warp = tid >> 5;
    const int qi = 15 - (int)blockIdx.x;        // heavy q-tiles first
    const int bh = blockIdx.y;
    const int q0 = qi << 7;
    const int nkv = 2 * qi + 2;
    u32 sb = (u32)__cvta_generic_to_shared(smem);

    const int g = lane >> 3, rsel = lane & 7;
    const size_t base = (size_t)bh * SEQ * 128;

    // ---- Q loads (resident region: Qh @0, Ql @34816), one commit group ----
#pragma unroll
    for (int i = 0; i < 8; i++) {
        int idx = i * 256 + tid;                 // 0..2047
        int row = idx >> 4, c = idx & 15;
        u32 d = sb + (u32)(row * 272 + c * 16);
        size_t s = base + (size_t)(q0 + row) * 128 + c * 8;
        cpa16(d,         qhp + s);
        cpa16(d + 34816, qlp + s);
    }
    asm volatile("cp.async.commit_group;" ::: "memory");

    auto load_kv = [&](int kt) {
        u32 st = sb + (u32)(FSTG + (kt & 1) * FSTG);
        const size_t rb = base + (size_t)(kt * 64) * 128;
#pragma unroll
        for (int i = 0; i < 4; i++) {
            int idx = i * 256 + tid;             // 0..1023
            int row = idx >> 4, c = idx & 15;
            u32 d = st + (u32)(row * 272 + c * 16);
            size_t s = rb + (size_t)row * 128 + c * 8;
            cpa16(d,         khp + s);
            cpa16(d + 17408, klp + s);
            cpa16(d + 34816, vhp + s);
            cpa16(d + 52224, vlp + s);
        }
        asm volatile("cp.async.commit_group;" ::: "memory");
    };

    load_kv(0);

    float oacc[16][4];
#pragma unroll
    for (int i = 0; i < 16; i++)
#pragma unroll
        for (int j = 0; j < 4; j++) oacc[i][j] = 0.f;
    float lsum0 = 0.f, lsum1 = 0.f;

    const u32 qoff = sb + (u32)((warp * 16 + (g & 1) * 8 + rsel) * 272 + (g >> 1) * 16);
    const int rowq = warp * 16 + (lane >> 2);        // local q row (of pair)

    for (int kt = 0; kt < nkv; kt++) {
        asm volatile("cp.async.wait_group 0;" ::: "memory");
        __syncthreads();
        if (kt + 1 < nkv) load_kv(kt + 1);
        u32 st = sb + (u32)(FSTG + (kt & 1) * FSTG);

        // ---- S = Q K^T  (bf16x3, product-major) ----
        float sacc[8][4];
#pragma unroll
        for (int i = 0; i < 8; i++)
#pragma unroll
            for (int j = 0; j < 4; j++) sacc[i][j] = 0.f;

        const u32 kb = st + (u32)(((g >> 1) * 8 + rsel) * 272 + (g & 1) * 16);
#pragma unroll
        for (int ks = 0; ks < 8; ks++) {
            u32 ah4[4], al4[4];
            ldsm4(ah4, qoff + ks * 32);
            ldsm4(al4, qoff + 34816 + ks * 32);
            u32 tb[4][4], tl[4][4];
#pragma unroll
            for (int ng = 0; ng < 4; ng++) {
                ldsm4(tb[ng], kb + ng * (16 * 272) + ks * 32);
                ldsm4(tl[ng], kb + 17408 + ng * (16 * 272) + ks * 32);
            }
#pragma unroll
            for (int ng = 0; ng < 4; ng++) {
                mma_bf16(sacc[2 * ng],     ah4, tb[ng]);
                mma_bf16(sacc[2 * ng + 1], ah4, tb[ng] + 2);
            }
#pragma unroll
            for (int ng = 0; ng < 4; ng++) {
                mma_bf16(sacc[2 * ng],     al4, tb[ng]);
                mma_bf16(sacc[2 * ng + 1], al4, tb[ng] + 2);
            }
#pragma unroll
            for (int ng = 0; ng < 4; ng++) {
                mma_bf16(sacc[2 * ng],     ah4, tl[ng]);
                mma_bf16(sacc[2 * ng + 1], ah4, tl[ng] + 2);
            }
        }

        // ---- softmax numerator (no max-subtraction; scores are O(1)) ----
        const bool diag = (kt >= 2 * qi);
        const int row0 = q0 + rowq;
        const int colb = kt * 64 + 2 * (lane & 3);
        u32 pah[4][4], pal[4][4];
#pragma unroll
        for (int ni = 0; ni < 8; ni++) {
            int c0 = colb + ni * 8;
            float p0, p1, p2, p3;
            if (diag) {
                p0 = (c0     <= row0    ) ? fexp(sacc[ni][0]) : 0.f;
                p1 = (c0 + 1 <= row0    ) ? fexp(sacc[ni][1]) : 0.f;
                p2 = (c0     <= row0 + 8) ? fexp(sacc[ni][2]) : 0.f;
                p3 = (c0 + 1 <= row0 + 8) ? fexp(sacc[ni][3]) : 0.f;
            } else {
                p0 = fexp(sacc[ni][0]); p1 = fexp(sacc[ni][1]);
                p2 = fexp(sacc[ni][2]); p3 = fexp(sacc[ni][3]);
            }
            lsum0 += p0 + p1;
            lsum1 += p2 + p3;
            int kt2 = ni >> 1, j = (ni & 1) * 2;
            split2(p0, p1, pah[kt2][j],     pal[kt2][j]);
            split2(p2, p3, pah[kt2][j + 1], pal[kt2][j + 1]);
        }

        // ---- O += P V  (bf16x3, V via trans ldmatrix, dg pairs) ----
        const u32 vb = st + 34816 + (u32)(((g & 1) * 8 + rsel) * 272 + (g >> 1) * 16);
#pragma unroll
        for (int kt2 = 0; kt2 < 4; kt2++) {
#pragma unroll
            for (int dgp = 0; dgp < 4; dgp++) {
                u32 th0[4], th1[4], tl0[4], tl1[4];
                u32 vbb = vb + kt2 * (16 * 272) + dgp * 64;
                ldsm4t(th0, vbb);
                ldsm4t(th1, vbb + 32);
                ldsm4t(tl0, vbb + 17408);
                ldsm4t(tl1, vbb + 17408 + 32);
                float* o0 = oacc[4 * dgp];
                float* o1 = oacc[4 * dgp + 1];
                float* o2 = oacc[4 * dgp + 2];
                float* o3 = oacc[4 * dgp + 3];
                mma_bf16(o0, pah[kt2], th0);
                mma_bf16(o1, pah[kt2], th0 + 2);
                mma_bf16(o2, pah[kt2], th1);
                mma_bf16(o3, pah[kt2], th1 + 2);
                mma_bf16(o0, pal[kt2], th0);
                mma_bf16(o1, pal[kt2], th0 + 2);
                mma_bf16(o2, pal[kt2], th1);
                mma_bf16(o3, pal[kt2], th1 + 2);
                mma_bf16(o0, pah[kt2], tl0);
                mma_bf16(o1, pah[kt2], tl0 + 2);
                mma_bf16(o2, pah[kt2], tl1);
                mma_bf16(o3, pah[kt2], tl1 + 2);
            }
        }
    }

    // ---- normalize + pre-split store into g_ah/g_al ----
    lsum0 += __shfl_xor_sync(0xffffffffu, lsum0, 1);
    lsum0 += __shfl_xor_sync(0xffffffffu, lsum0, 2);
    lsum1 += __shfl_xor_sync(0xffffffffu, lsum1, 1);
    lsum1 += __shfl_xor_sync(0xffffffffu, lsum1, 2);
    float inv0 = 1.f / lsum0, inv1 = 1.f / lsum1;

    const int b = bh >> 4, h = bh & 15;
    const int r0 = q0 + rowq;
    size_t obase0 = ((size_t)(b * SEQ + r0)) * HID + h * 128;
    size_t obase1 = obase0 + (size_t)8 * HID;
#pragma unroll
    for (int dt = 0; dt < 16; dt++) {
        int col = dt * 8 + 2 * (lane & 3);
        u32 hi0, lo0, hi1, lo1;
        split2(oacc[dt][0] * inv0, oacc[dt][1] * inv0, hi0, lo0);
        split2(oacc[dt][2] * inv1, oacc[dt][3] * inv1, hi1, lo1);
        *(u32*)(oh + obase0 + col) = hi0;
        *(u32*)(ol + obase0 + col) = lo0;
        *(u32*)(oh + obase1 + col) = hi1;
        *(u32*)(ol + obase1 + col) = lo1;
    }
}

// ---------------------------------------------------------------------------
extern "C" void kernel_launch(void* const* d_in, const int* in_sizes, int n_in,
                              void* d_out, int out_size)
{
    const float* hidden = (const float*)d_in[0];
    const float* qkvk = (const float*)d_in[2];
    const float* qkvb = (const float*)d_in[3];
    const float* outk = (const float*)d_in[4];
    const float* outb = (const float*)d_in[5];
    float* out = (float*)d_out;

    float* pqkv;
    __nv_bfloat16 *pqh, *pql, *pkh, *pkl, *pvh, *pvl, *pah, *pal, *pbh, *pbl;
    cudaGetSymbolAddress((void**)&pqkv, g_qkv);
    cudaGetSymbolAddress((void**)&pqh,  g_qh);
    cudaGetSymbolAddress((void**)&pql,  g_ql);
    cudaGetSymbolAddress((void**)&pkh,  g_kh);
    cudaGetSymbolAddress((void**)&pkl,  g_kl);
    cudaGetSymbolAddress((void**)&pvh,  g_vh);
    cudaGetSymbolAddress((void**)&pvl,  g_vl);
    cudaGetSymbolAddress((void**)&pah,  g_ah);
    cudaGetSymbolAddress((void**)&pal,  g_al);
    cudaGetSymbolAddress((void**)&pbh,  g_bh);
    cudaGetSymbolAddress((void**)&pbl,  g_bl);

    cudaFuncSetAttribute((const void*)gemm_mma,
                         cudaFuncAttributeMaxDynamicSharedMemorySize, 3 * GST);
    cudaFuncSetAttribute((const void*)flash_mma,
                         cudaFuncAttributeMaxDynamicSharedMemorySize, 3 * FSTG);

    // --- QKV projection: [4096,2048] @ [2048,6144] + bias ---
    split_rm<<<(4096 * 2048 / 4 + 255) / 256, 256>>>((const float4*)hidden, pah, pal, 4096 * 2048 / 4);
    tsplit<<<dim3(6144 / 32, 2048 / 32), dim3(32, 8)>>>(qkvk, pbh, pbl, 2048, 6144);
    gemm_mma<<<dim3(48, 32), 256, 3 * GST>>>(pah, pal, pbh, pbl, qkvb, pqkv, 4096, 6144, 2048);

    // --- RoPE + hi/lo split ---
    rope_split<<<32 * SEQ * 128 / 256, 256>>>(pqkv, pqh, pql, pkh, pkl, pvh, pvl);

    // --- causal flash attention (HMMA), writes pre-split A for out-proj ---
    flash_mma<<<dim3(16, 32), 256, 3 * FSTG>>>(pqh, pql, pkh, pkl, pvh, pvl, pah, pal);

    // --- output projection: [4096,2048] @ [2048,2048] + bias ---
    tsplit<<<dim3(2048 / 32, 2048 / 32), dim3(32, 8)>>>(outk, pbh, pbl, 2048, 2048);
    gemm_mma<<<dim3(16, 32), 256, 3 * GST>>>(pah, pal, pbh, pbl, outb, out, 4096, 2048, 2048);
}

// round 13
// speedup vs baseline: 3.5004x; 1.3340x over previous
#include <cuda_runtime.h>
#include <cuda_fp16.h>
#include <math.h>
#include <stdint.h>

#define SEQ    2048
#define NQKV   6144
#define HID    2048

typedef unsigned long long u64;
typedef unsigned int u32;

// ------------------------- scratch (device globals) -------------------------
__device__ float g_qkv [(size_t)2 * SEQ * NQKV];      // [b*s][6144]
__device__ __half g_qh[(size_t)32 * SEQ * 128];       // Q hi  [bh][s][d]
__device__ __half g_ql[(size_t)32 * SEQ * 128];       // Q lo
__device__ __half g_kh[(size_t)32 * SEQ * 128];       // K single
__device__ __half g_vh[(size_t)32 * SEQ * 128];       // V single
__device__ __half g_ah[(size_t)4096 * 2048];          // A hi  [M][K] (activations)
__device__ __half g_al[(size_t)4096 * 2048];          // A lo
__device__ __half g_bh[(size_t)6144 * 2048];          // B^T single [N][K] (weights)

// ------------------------- async / mma helpers (base PTX only) ---------------
__device__ __forceinline__ void cpa16(u32 dst, const void* src) {
    asm volatile("cp.async.cg.shared.global [%0], [%1], 16;" :: "r"(dst), "l"(src));
}
__device__ __forceinline__ void ldsm4(u32 r[4], u32 addr) {
    asm volatile("ldmatrix.sync.aligned.m8n8.x4.shared.b16 {%0,%1,%2,%3}, [%4];"
                 : "=r"(r[0]), "=r"(r[1]), "=r"(r[2]), "=r"(r[3]) : "r"(addr));
}
__device__ __forceinline__ void ldsm4t(u32 r[4], u32 addr) {
    asm volatile("ldmatrix.sync.aligned.m8n8.x4.trans.shared.b16 {%0,%1,%2,%3}, [%4];"
                 : "=r"(r[0]), "=r"(r[1]), "=r"(r[2]), "=r"(r[3]) : "r"(addr));
}
__device__ __forceinline__ void mma_f16(float c[4], const u32 a[4], const u32 b[2]) {
    asm volatile("mma.sync.aligned.m16n8k16.row.col.f32.f16.f16.f32 "
                 "{%0,%1,%2,%3}, {%4,%5,%6,%7}, {%8,%9}, {%0,%1,%2,%3};"
                 : "+f"(c[0]), "+f"(c[1]), "+f"(c[2]), "+f"(c[3])
                 : "r"(a[0]), "r"(a[1]), "r"(a[2]), "r"(a[3]), "r"(b[0]), "r"(b[1]));
}

// fast exp on the FMA pipe (rel err ~2.4e-6)
__device__ __forceinline__ float fexp(float x) {
    float t = fmaxf(x, -80.f) * 1.4426950408889634f;
    float z = t + 12582912.f;
    int e = __float_as_int(z) - 0x4B400000;
    float f = t - (z - 12582912.f);
    float g = f * 0.6931471805599453f;
    float r = fmaf(g, 0.0083333333f, 0.0416666667f);
    r = fmaf(g, r, 0.16666667f);
    r = fmaf(g, r, 0.5f);
    r = fmaf(g, r, 1.0f);
    r = fmaf(g, r, 1.0f);
    return r * __int_as_float((e + 127) << 23);
}

// split two floats into packed fp16 hi-pair and lo-pair
__device__ __forceinline__ void split2h(float a, float b, u32 &hi, u32 &lo) {
    __half2 h = __floats2half2_rn(a, b);
    hi = *(u32*)&h;
    float ra = a - __half2float(__low2half(h));
    float rb = b - __half2float(__high2half(h));
    __half2 l = __floats2half2_rn(ra, rb);
    lo = *(u32*)&l;
}

// ---------------------------------------------------------------------------
// fp32 -> fp16 hi/lo split (row-major activations)
// ---------------------------------------------------------------------------
__global__ void split_rm(const float4* __restrict__ x, __half* __restrict__ hi,
                         __half* __restrict__ lo, int n4)
{
    int i = blockIdx.x * 256 + threadIdx.x;
    if (i >= n4) return;
    float4 v = x[i];
    float a[4] = {v.x, v.y, v.z, v.w};
    __half H[4], L[4];
#pragma unroll
    for (int j = 0; j < 4; j++) {
        H[j] = __float2half(a[j]);
        L[j] = __float2half(a[j] - __half2float(H[j]));
    }
    *(uint2*)(hi + 4 * (size_t)i) = *(uint2*)H;
    *(uint2*)(lo + 4 * (size_t)i) = *(uint2*)L;
}

// W [K][N] row-major -> single fp16 [N][K]  (tiled smem transpose)
__global__ void tsplit(const float* __restrict__ w, __half* __restrict__ hi,
                       int K, int N)
{
    __shared__ float t[32][33];
    const int k0 = blockIdx.y << 5, n0 = blockIdx.x << 5;
    const int tx = threadIdx.x, ty = threadIdx.y;   // 32 x 8
#pragma unroll
    for (int i = 0; i < 4; i++)
        t[ty + 8 * i][tx] = w[(size_t)(k0 + ty + 8 * i) * N + n0 + tx];
    __syncthreads();
#pragma unroll
    for (int i = 0; i < 4; i++)
        hi[(size_t)(n0 + ty + 8 * i) * K + k0 + tx] = __float2half(t[tx][ty + 8 * i]);
}

// ---------------------------------------------------------------------------
// fp16x2 GEMM via mma.sync:  C[M,N] = A[M,K] @ B^T[N,K]^T + bias[N]
// A split hi/lo (exact), B single fp16.  128x128 tile, BK=32, 8 warps.
// 3-stage cp.async ring, one __syncthreads per iter.
// ---------------------------------------------------------------------------
#define GST 30720   // Ah 10240 | Al 10240 | B 10240

__global__ __launch_bounds__(256, 1)
void gemm_mma(const __half* __restrict__ Ahp, const __half* __restrict__ Alp,
              const __half* __restrict__ Bhp,
              const float* __restrict__ bias, float* __restrict__ C,
              int M, int N, int K)
{
    extern __shared__ __align__(16) char smem[];
    const int tid = threadIdx.x, lane = tid & 31, warp = tid >> 5;
    const int wm = warp & 1, wn = warp >> 1;
    const int mBase = blockIdx.y * 128, nBase = blockIdx.x * 128;
    u32 sb = (u32)__cvta_generic_to_shared(smem);

    const int g = lane >> 3, rsel = lane & 7;
    const u32 offA = (u32)((wm * 64 + (g & 1) * 8 + rsel) * 80 + (g >> 1) * 16);
    const u32 offB = (u32)((wn * 32 + (g >> 1) * 8 + rsel) * 80 + (g & 1) * 16);

    float acc[4][4][4];
#pragma unroll
    for (int a = 0; a < 4; a++)
#pragma unroll
        for (int b = 0; b < 4; b++)
#pragma unroll
            for (int c = 0; c < 4; c++) acc[a][b][c] = 0.f;

    const int niter = K >> 5;

    auto load_stage = [&](int stage, int kc) {
        u32 st = sb + (u32)stage * GST;
#pragma unroll
        for (int i = 0; i < 2; i++) {
            int ch = i * 256 + tid;              // 0..511
            int row = ch >> 2, c = ch & 3;
            u32 d = st + (u32)(row * 80 + c * 16);
            size_t aoff = (size_t)(mBase + row) * K + kc * 32 + c * 8;
            cpa16(d,         Ahp + aoff);
            cpa16(d + 10240, Alp + aoff);
        }
#pragma unroll
        for (int i = 0; i < 2; i++) {
            int ch = i * 256 + tid;
            int row = ch >> 2, c = ch & 3;
            u32 d = st + 20480 + (u32)(row * 80 + c * 16);
            cpa16(d, Bhp + (size_t)(nBase + row) * K + kc * 32 + c * 8);
        }
        asm volatile("cp.async.commit_group;" ::: "memory");
    };

    load_stage(0, 0);
    load_stage(1, 1);

    for (int it = 0; it < niter; it++) {
        if (it + 1 < niter) {
            asm volatile("cp.async.wait_group 1;" ::: "memory");
        } else {
            asm volatile("cp.async.wait_group 0;" ::: "memory");
        }
        __syncthreads();
        if (it + 2 < niter) load_stage((it + 2) % 3, it + 2);

        u32 st = sb + (u32)(it % 3) * GST;
#pragma unroll
        for (int ks = 0; ks < 2; ks++) {
            u32 ah[4][4], al[4][4], bh[4][2];
#pragma unroll
            for (int mi = 0; mi < 4; mi++) {
                u32 a = st + offA + (u32)(mi * 16 * 80 + ks * 32);
                ldsm4(ah[mi], a);
                ldsm4(al[mi], a + 10240);
            }
#pragma unroll
            for (int nh = 0; nh < 2; nh++) {
                u32 b = st + 20480 + offB + (u32)(nh * 16 * 80 + ks * 32);
                u32 t[4];
                ldsm4(t, b);
                bh[2 * nh][0] = t[0]; bh[2 * nh][1] = t[1];
                bh[2 * nh + 1][0] = t[2]; bh[2 * nh + 1][1] = t[3];
            }
#pragma unroll
            for (int mi = 0; mi < 4; mi++)
#pragma unroll
                for (int ni = 0; ni < 4; ni++)
                    mma_f16(acc[mi][ni], ah[mi], bh[ni]);
#pragma unroll
            for (int mi = 0; mi < 4; mi++)
#pragma unroll
                for (int ni = 0; ni < 4; ni++)
                    mma_f16(acc[mi][ni], al[mi], bh[ni]);
        }
    }

    __syncthreads();
    const int q = lane >> 2, t2 = (lane & 3) * 2;
#pragma unroll
    for (int mi = 0; mi < 4; mi++) {
        int r0 = mBase + wm * 64 + mi * 16 + q;
#pragma unroll
        for (int ni = 0; ni < 4; ni++) {
            int col = nBase + wn * 32 + ni * 8 + t2;
            float b0 = bias[col], b1 = bias[col + 1];
            *(float2*)&C[(size_t)r0 * N + col] =
                make_float2(acc[mi][ni][0] + b0, acc[mi][ni][1] + b1);
            *(float2*)&C[(size_t)(r0 + 8) * N + col] =
                make_float2(acc[mi][ni][2] + b0, acc[mi][ni][3] + b1);
        }
    }
}

// ---------------------------------------------------------------------------
// RoPE + fp16 conversion:  g_qkv [b*s][h*384+{q,k,v}] ->
//   Q as hi/lo fp16 (exact split), K and V single fp16, all [bh][s][128].
//   Q pre-scaled by 1/sqrt(128).
// ---------------------------------------------------------------------------
__global__ __launch_bounds__(256)
void rope_split(const float* __restrict__ qkv,
                __half* __restrict__ qh, __half* __restrict__ ql,
                __half* __restrict__ kh, __half* __restrict__ vh)
{
    int idx = blockIdx.x * 256 + threadIdx.x;     // over 32*2048*128
    int d = idx & 127;
    int s = (idx >> 7) & 2047;
    int bh = idx >> 18;
    int b = bh >> 4, h = bh & 15;

    const float* src = qkv + ((size_t)(b * SEQ + s)) * NQKV + h * 384;
    float qv = src[d], kv = src[128 + d], vv = src[256 + d];

    if (d < 32) {
        int fi = d & 15;
        float invf = expf(-(float)fi * (9.210340371976184f / 16.0f));
        float sn, cs;
        sincosf((float)s * invf, &sn, &cs);
        float q2 = (d < 16) ? -src[d + 16]       : src[d - 16];
        float k2 = (d < 16) ? -src[128 + d + 16] : src[128 + d - 16];
        qv = qv * cs + q2 * sn;
        kv = kv * cs + k2 * sn;
    }
    qv *= 0.08838834764831843f;   // 1/sqrt(128)

    size_t o = (size_t)bh * SEQ * 128 + (size_t)s * 128 + d;
    __half x = __float2half(qv);
    qh[o] = x;
    ql[o] = __float2half(qv - __half2float(x));
    kh[o] = __float2half(kv);
    vh[o] = __float2half(vv);
}

// ---------------------------------------------------------------------------
// Flash attention via mma.sync, fp16x2, causal, no-max softmax.
// BQ=128 (8 warps x 16 rows), BKV=64, D=128.
// Q hi/lo resident (69632B); KV stages 34816B each (K single + V single).
// Output written pre-split (fp16 hi/lo) into g_ah/g_al for the out-proj.
// ---------------------------------------------------------------------------
#define FKV 34816
#define FL_SMEM (69632 + 2 * FKV)

__global__ __launch_bounds__(256, 1)
void flash_mma(const __half* __restrict__ qhp, const __half* __restrict__ qlp,
               const __half* __restrict__ khp, const __half* __restrict__ vhp,
               __half* __restrict__ oh, __half* __restrict__ ol)
{
    extern __shared__ __align__(16) char smem[];
    const int tid = threadIdx.x, lane = tid & 31, warp = tid >> 5;
    const int qi = 15 - (int)blockIdx.x;        // heavy q-tiles first
    const int bh = blockIdx.y;
    const int q0 = qi << 7;
    const int nkv = 2 * qi + 2;
    u32 sb = (u32)__cvta_generic_to_shared(smem);

    const int g = lane >> 3, rsel = lane & 7;
    const size_t base = (size_t)bh * SEQ * 128;

    // ---- Q loads (resident: Qh @0, Ql @34816) ----
#pragma unroll
    for (int i = 0; i < 8; i++) {
        int idx = i * 256 + tid;                 // 0..2047
        int row = idx >> 4, c = idx & 15;
        u32 d = sb + (u32)(row * 272 + c * 16);
        size_t s = base + (size_t)(q0 + row) * 128 + c * 8;
        cpa16(d,         qhp + s);
        cpa16(d + 34816, qlp + s);
    }
    asm volatile("cp.async.commit_group;" ::: "memory");

    auto load_kv = [&](int kt) {
        u32 st = sb + (u32)(69632 + (kt & 1) * FKV);
        const size_t rb = base + (size_t)(kt * 64) * 128;
#pragma unroll
        for (int i = 0; i < 2; i++) {
            int idx = i * 256 + tid;             // 0..511
            int row = idx >> 3, c = idx & 7;     // 64 rows x 8 chunks
            u32 d = st + (u32)(row * 272 + c * 32);
            size_t s = rb + (size_t)row * 128 + c * 16;
            cpa16(d,          khp + s);
            cpa16(d + 16,     khp + s + 8);
            cpa16(d + 17408,      vhp + s);
            cpa16(d + 17408 + 16, vhp + s + 8);
        }
        asm volatile("cp.async.commit_group;" ::: "memory");
    };

    load_kv(0);

    float oacc[16][4];
#pragma unroll
    for (int i = 0; i < 16; i++)
#pragma unroll
        for (int j = 0; j < 4; j++) oacc[i][j] = 0.f;
    float lsum0 = 0.f, lsum1 = 0.f;

    const u32 qoff = sb + (u32)((warp * 16 + (g & 1) * 8 + rsel) * 272 + (g >> 1) * 16);
    const int rowq = warp * 16 + (lane >> 2);        // local q row (of pair)

    for (int kt = 0; kt < nkv; kt++) {
        asm volatile("cp.async.wait_group 0;" ::: "memory");
        __syncthreads();
        if (kt + 1 < nkv) load_kv(kt + 1);
        u32 st = sb + (u32)(69632 + (kt & 1) * FKV);

        // ---- S = Q K^T  (Q split exact, K single) ----
        float sacc[8][4];
#pragma unroll
        for (int i = 0; i < 8; i++)
#pragma unroll
            for (int j = 0; j < 4; j++) sacc[i][j] = 0.f;

        const u32 kb = st + (u32)(((g >> 1) * 8 + rsel) * 272 + (g & 1) * 16);
#pragma unroll
        for (int ks = 0; ks < 8; ks++) {
            u32 qh4[4], ql4[4];
            ldsm4(qh4, qoff + ks * 32);
            ldsm4(ql4, qoff + 34816 + ks * 32);
            u32 tb[4][4];
#pragma unroll
            for (int ng = 0; ng < 4; ng++)
                ldsm4(tb[ng], kb + ng * (16 * 272) + ks * 32);
#pragma unroll
            for (int ng = 0; ng < 4; ng++) {
                mma_f16(sacc[2 * ng],     qh4, tb[ng]);
                mma_f16(sacc[2 * ng + 1], qh4, tb[ng] + 2);
            }
#pragma unroll
            for (int ng = 0; ng < 4; ng++) {
                mma_f16(sacc[2 * ng],     ql4, tb[ng]);
                mma_f16(sacc[2 * ng + 1], ql4, tb[ng] + 2);
            }
        }

        // ---- softmax numerator (no max-subtraction; scores are O(1)) ----
        const bool diag = (kt >= 2 * qi);
        const int row0 = q0 + rowq;
        const int colb = kt * 64 + 2 * (lane & 3);
        u32 pah[4][4], pal[4][4];
#pragma unroll
        for (int ni = 0; ni < 8; ni++) {
            int c0 = colb + ni * 8;
            float p0, p1, p2, p3;
            if (diag) {
                p0 = (c0     <= row0    ) ? fexp(sacc[ni][0]) : 0.f;
                p1 = (c0 + 1 <= row0    ) ? fexp(sacc[ni][1]) : 0.f;
                p2 = (c0     <= row0 + 8) ? fexp(sacc[ni][2]) : 0.f;
                p3 = (c0 + 1 <= row0 + 8) ? fexp(sacc[ni][3]) : 0.f;
            } else {
                p0 = fexp(sacc[ni][0]); p1 = fexp(sacc[ni][1]);
                p2 = fexp(sacc[ni][2]); p3 = fexp(sacc[ni][3]);
            }
            lsum0 += p0 + p1;
            lsum1 += p2 + p3;
            int kt2 = ni >> 1, j = (ni & 1) * 2;
            split2h(p0, p1, pah[kt2][j],     pal[kt2][j]);
            split2h(p2, p3, pah[kt2][j + 1], pal[kt2][j + 1]);
        }

        // ---- O += P V  (P split exact, V single; trans ldmatrix) ----
        const u32 vb = st + 17408 + (u32)(((g & 1) * 8 + rsel) * 272 + (g >> 1) * 16);
#pragma unroll
        for (int kt2 = 0; kt2 < 4; kt2++) {
#pragma unroll
            for (int dgp = 0; dgp < 4; dgp++) {
                u32 th0[4], th1[4];
                u32 vbb = vb + kt2 * (16 * 272) + dgp * 64;
                ldsm4t(th0, vbb);
                ldsm4t(th1, vbb + 32);
                float* o0 = oacc[4 * dgp];
                float* o1 = oacc[4 * dgp + 1];
                float* o2 = oacc[4 * dgp + 2];
                float* o3 = oacc[4 * dgp + 3];
                mma_f16(o0, pah[kt2], th0);
                mma_f16(o1, pah[kt2], th0 + 2);
                mma_f16(o2, pah[kt2], th1);
                mma_f16(o3, pah[kt2], th1 + 2);
                mma_f16(o0, pal[kt2], th0);
                mma_f16(o1, pal[kt2], th0 + 2);
                mma_f16(o2, pal[kt2], th1);
                mma_f16(o3, pal[kt2], th1 + 2);
            }
        }
    }

    // ---- normalize + pre-split store into g_ah/g_al ----
    lsum0 += __shfl_xor_sync(0xffffffffu, lsum0, 1);
    lsum0 += __shfl_xor_sync(0xffffffffu, lsum0, 2);
    lsum1 += __shfl_xor_sync(0xffffffffu, lsum1, 1);
    lsum1 += __shfl_xor_sync(0xffffffffu, lsum1, 2);
    float inv0 = 1.f / lsum0, inv1 = 1.f / lsum1;

    const int b = bh >> 4, h = bh & 15;
    const int r0 = q0 + rowq;
    size_t obase0 = ((size_t)(b * SEQ + r0)) * HID + h * 128;
    size_t obase1 = obase0 + (size_t)8 * HID;
#pragma unroll
    for (int dt = 0; dt < 16; dt++) {
        int col = dt * 8 + 2 * (lane & 3);
        u32 hi0, lo0, hi1, lo1;
        split2h(oacc[dt][0] * inv0, oacc[dt][1] * inv0, hi0, lo0);
        split2h(oacc[dt][2] * inv1, oacc[dt][3] * inv1, hi1, lo1);
        *(u32*)(oh + obase0 + col) = hi0;
        *(u32*)(ol + obase0 + col) = lo0;
        *(u32*)(oh + obase1 + col) = hi1;
        *(u32*)(ol + obase1 + col) = lo1;
    }
}

// ---------------------------------------------------------------------------
extern "C" void kernel_launch(void* const* d_in, const int* in_sizes, int n_in,
                              void* d_out, int out_size)
{
    const float* hidden = (const float*)d_in[0];
    const float* qkvk = (const float*)d_in[2];
    const float* qkvb = (const float*)d_in[3];
    const float* outk = (const float*)d_in[4];
    const float* outb = (const float*)d_in[5];
    float* out = (float*)d_out;

    float* pqkv;
    __half *pqh, *pql, *pkh, *pvh, *pah, *pal, *pbh;
    cudaGetSymbolAddress((void**)&pqkv, g_qkv);
    cudaGetSymbolAddress((void**)&pqh,  g_qh);
    cudaGetSymbolAddress((void**)&pql,  g_ql);
    cudaGetSymbolAddress((void**)&pkh,  g_kh);
    cudaGetSymbolAddress((void**)&pvh,  g_vh);
    cudaGetSymbolAddress((void**)&pah,  g_ah);
    cudaGetSymbolAddress((void**)&pal,  g_al);
    cudaGetSymbolAddress((void**)&pbh,  g_bh);

    cudaFuncSetAttribute((const void*)gemm_mma,
                         cudaFuncAttributeMaxDynamicSharedMemorySize, 3 * GST);
    cudaFuncSetAttribute((const void*)flash_mma,
                         cudaFuncAttributeMaxDynamicSharedMemorySize, FL_SMEM);

    // --- QKV projection: [4096,2048] @ [2048,6144] + bias ---
    split_rm<<<(4096 * 2048 / 4 + 255) / 256, 256>>>((const float4*)hidden, pah, pal, 4096 * 2048 / 4);
    tsplit<<<dim3(6144 / 32, 2048 / 32), dim3(32, 8)>>>(qkvk, pbh, 2048, 6144);
    gemm_mma<<<dim3(48, 32), 256, 3 * GST>>>(pah, pal, pbh, qkvb, pqkv, 4096, 6144, 2048);

    // --- RoPE + fp16 conversion ---
    rope_split<<<32 * SEQ * 128 / 256, 256>>>(pqkv, pqh, pql, pkh, pvh);

    // --- causal flash attention (fp16x2 HMMA), writes pre-split out-proj A ---
    flash_mma<<<dim3(16, 32), 256, FL_SMEM>>>(pqh, pql, pkh, pvh, pah, pal);

    // --- output projection: [4096,2048] @ [2048,2048] + bias ---
    tsplit<<<dim3(2048 / 32, 2048 / 32), dim3(32, 8)>>>(outk, pbh, 2048, 2048);
    gemm_mma<<<dim3(16, 32), 256, 3 * GST>>>(pah, pal, pbh, outb, out, 4096, 2048, 2048);
}

// round 14
// speedup vs baseline: 3.7027x; 1.0578x over previous
#include <cuda_runtime.h>
#include <cuda_fp16.h>
#include <math.h>
#include <stdint.h>

#define SEQ    2048
#define NQKV   6144
#define HID    2048

typedef unsigned long long u64;
typedef unsigned int u32;

// ------------------------- scratch (device globals) -------------------------
__device__ __half g_qh[(size_t)32 * SEQ * 128];       // Q single (pre-scaled) [bh][s][d]
__device__ __half g_kh[(size_t)32 * SEQ * 128];       // K single
__device__ __half g_vh[(size_t)32 * SEQ * 128];       // V single
__device__ __half g_ah[(size_t)4096 * 2048];          // A hi  [M][K] (activations)
__device__ __half g_al[(size_t)4096 * 2048];          // A lo
__device__ __half g_bh[(size_t)6144 * 2048];          // B^T single [N][K] (weights)

// ------------------------- async / mma helpers (base PTX only) ---------------
__device__ __forceinline__ void cpa16(u32 dst, const void* src) {
    asm volatile("cp.async.cg.shared.global [%0], [%1], 16;" :: "r"(dst), "l"(src));
}
__device__ __forceinline__ void ldsm4(u32 r[4], u32 addr) {
    asm volatile("ldmatrix.sync.aligned.m8n8.x4.shared.b16 {%0,%1,%2,%3}, [%4];"
                 : "=r"(r[0]), "=r"(r[1]), "=r"(r[2]), "=r"(r[3]) : "r"(addr));
}
__device__ __forceinline__ void ldsm4t(u32 r[4], u32 addr) {
    asm volatile("ldmatrix.sync.aligned.m8n8.x4.trans.shared.b16 {%0,%1,%2,%3}, [%4];"
                 : "=r"(r[0]), "=r"(r[1]), "=r"(r[2]), "=r"(r[3]) : "r"(addr));
}
__device__ __forceinline__ void mma_f16(float c[4], const u32 a[4], const u32 b[2]) {
    asm volatile("mma.sync.aligned.m16n8k16.row.col.f32.f16.f16.f32 "
                 "{%0,%1,%2,%3}, {%4,%5,%6,%7}, {%8,%9}, {%0,%1,%2,%3};"
                 : "+f"(c[0]), "+f"(c[1]), "+f"(c[2]), "+f"(c[3])
                 : "r"(a[0]), "r"(a[1]), "r"(a[2]), "r"(a[3]), "r"(b[0]), "r"(b[1]));
}

// fast exp on the FMA pipe (rel err ~2.4e-6)
__device__ __forceinline__ float fexp(float x) {
    float t = fmaxf(x, -80.f) * 1.4426950408889634f;
    float z = t + 12582912.f;
    int e = __float_as_int(z) - 0x4B400000;
    float f = t - (z - 12582912.f);
    float g = f * 0.6931471805599453f;
    float r = fmaf(g, 0.0083333333f, 0.0416666667f);
    r = fmaf(g, r, 0.16666667f);
    r = fmaf(g, r, 0.5f);
    r = fmaf(g, r, 1.0f);
    r = fmaf(g, r, 1.0f);
    return r * __int_as_float((e + 127) << 23);
}

// split two floats into packed fp16 hi-pair and lo-pair
__device__ __forceinline__ void split2h(float a, float b, u32 &hi, u32 &lo) {
    __half2 h = __floats2half2_rn(a, b);
    hi = *(u32*)&h;
    float ra = a - __half2float(__low2half(h));
    float rb = b - __half2float(__high2half(h));
    __half2 l = __floats2half2_rn(ra, rb);
    lo = *(u32*)&l;
}

// ---------------------------------------------------------------------------
// fp32 -> fp16 hi/lo split (row-major activations)
// ---------------------------------------------------------------------------
__global__ void split_rm(const float4* __restrict__ x, __half* __restrict__ hi,
                         __half* __restrict__ lo, int n4)
{
    int i = blockIdx.x * 256 + threadIdx.x;
    if (i >= n4) return;
    float4 v = x[i];
    float a[4] = {v.x, v.y, v.z, v.w};
    __half H[4], L[4];
#pragma unroll
    for (int j = 0; j < 4; j++) {
        H[j] = __float2half(a[j]);
        L[j] = __float2half(a[j] - __half2float(H[j]));
    }
    *(uint2*)(hi + 4 * (size_t)i) = *(uint2*)H;
    *(uint2*)(lo + 4 * (size_t)i) = *(uint2*)L;
}

// W [K][N] row-major -> single fp16 [N][K]  (tiled smem transpose)
__global__ void tsplit(const float* __restrict__ w, __half* __restrict__ hi,
                       int K, int N)
{
    __shared__ float t[32][33];
    const int k0 = blockIdx.y << 5, n0 = blockIdx.x << 5;
    const int tx = threadIdx.x, ty = threadIdx.y;   // 32 x 8
#pragma unroll
    for (int i = 0; i < 4; i++)
        t[ty + 8 * i][tx] = w[(size_t)(k0 + ty + 8 * i) * N + n0 + tx];
    __syncthreads();
#pragma unroll
    for (int i = 0; i < 4; i++)
        hi[(size_t)(n0 + ty + 8 * i) * K + k0 + tx] = __float2half(t[tx][ty + 8 * i]);
}

// ---------------------------------------------------------------------------
// fp16x2 GEMM via mma.sync:  C[M,N] = A[M,K] @ B^T[N,K]^T + bias[N]
// A split hi/lo (exact), B single fp16.  128x128 tile, BK=32, 8 warps.
// mode 0: fp32 C store.
// mode 1: fused QKV epilogue — RoPE (thread-local pair rotation) + fp16
//         convert, writing q (scaled) / k / v directly in [bh][s][128].
// ---------------------------------------------------------------------------
#define GST 30720   // Ah 10240 | Al 10240 | B 10240

__global__ __launch_bounds__(256, 1)
void gemm_mma(const __half* __restrict__ Ahp, const __half* __restrict__ Alp,
              const __half* __restrict__ Bhp,
              const float* __restrict__ bias, float* __restrict__ C,
              int M, int N, int K, int mode,
              __half* __restrict__ qout, __half* __restrict__ kout,
              __half* __restrict__ vout)
{
    extern __shared__ __align__(16) char smem[];
    const int tid = threadIdx.x, lane = tid & 31, warp = tid >> 5;
    const int wm = warp & 1, wn = warp >> 1;
    const int mBase = blockIdx.y * 128, nBase = blockIdx.x * 128;
    u32 sb = (u32)__cvta_generic_to_shared(smem);

    const int g = lane >> 3, rsel = lane & 7;
    const u32 offA = (u32)((wm * 64 + (g & 1) * 8 + rsel) * 80 + (g >> 1) * 16);
    const u32 offB = (u32)((wn * 32 + (g >> 1) * 8 + rsel) * 80 + (g & 1) * 16);

    float acc[4][4][4];
#pragma unroll
    for (int a = 0; a < 4; a++)
#pragma unroll
        for (int b = 0; b < 4; b++)
#pragma unroll
            for (int c = 0; c < 4; c++) acc[a][b][c] = 0.f;

    const int niter = K >> 5;

    auto load_stage = [&](int stage, int kc) {
        u32 st = sb + (u32)stage * GST;
#pragma unroll
        for (int i = 0; i < 2; i++) {
            int ch = i * 256 + tid;              // 0..511
            int row = ch >> 2, c = ch & 3;
            u32 d = st + (u32)(row * 80 + c * 16);
            size_t aoff = (size_t)(mBase + row) * K + kc * 32 + c * 8;
            cpa16(d,         Ahp + aoff);
            cpa16(d + 10240, Alp + aoff);
        }
#pragma unroll
        for (int i = 0; i < 2; i++) {
            int ch = i * 256 + tid;
            int row = ch >> 2, c = ch & 3;
            u32 d = st + 20480 + (u32)(row * 80 + c * 16);
            cpa16(d, Bhp + (size_t)(nBase + row) * K + kc * 32 + c * 8);
        }
        asm volatile("cp.async.commit_group;" ::: "memory");
    };

    load_stage(0, 0);
    load_stage(1, 1);

    for (int it = 0; it < niter; it++) {
        if (it + 1 < niter) {
            asm volatile("cp.async.wait_group 1;" ::: "memory");
        } else {
            asm volatile("cp.async.wait_group 0;" ::: "memory");
        }
        __syncthreads();
        if (it + 2 < niter) load_stage((it + 2) % 3, it + 2);

        u32 st = sb + (u32)(it % 3) * GST;
#pragma unroll
        for (int ks = 0; ks < 2; ks++) {
            u32 ah[4][4], al[4][4], bh[4][2];
#pragma unroll
            for (int mi = 0; mi < 4; mi++) {
                u32 a = st + offA + (u32)(mi * 16 * 80 + ks * 32);
                ldsm4(ah[mi], a);
                ldsm4(al[mi], a + 10240);
            }
#pragma unroll
            for (int nh = 0; nh < 2; nh++) {
                u32 b = st + 20480 + offB + (u32)(nh * 16 * 80 + ks * 32);
                u32 t[4];
                ldsm4(t, b);
                bh[2 * nh][0] = t[0]; bh[2 * nh][1] = t[1];
                bh[2 * nh + 1][0] = t[2]; bh[2 * nh + 1][1] = t[3];
            }
#pragma unroll
            for (int mi = 0; mi < 4; mi++)
#pragma unroll
                for (int ni = 0; ni < 4; ni++)
                    mma_f16(acc[mi][ni], ah[mi], bh[ni]);
#pragma unroll
            for (int mi = 0; mi < 4; mi++)
#pragma unroll
                for (int ni = 0; ni < 4; ni++)
                    mma_f16(acc[mi][ni], al[mi], bh[ni]);
        }
    }

    __syncthreads();
    const int qrow = lane >> 2, t2 = (lane & 3) * 2;

    if (mode == 0) {
#pragma unroll
        for (int mi = 0; mi < 4; mi++) {
            int r0 = mBase + wm * 64 + mi * 16 + qrow;
#pragma unroll
            for (int ni = 0; ni < 4; ni++) {
                int col = nBase + wn * 32 + ni * 8 + t2;
                float b0 = bias[col], b1 = bias[col + 1];
                *(float2*)&C[(size_t)r0 * N + col] =
                    make_float2(acc[mi][ni][0] + b0, acc[mi][ni][1] + b1);
                *(float2*)&C[(size_t)(r0 + 8) * N + col] =
                    make_float2(acc[mi][ni][2] + b0, acc[mi][ni][3] + b1);
            }
        }
    } else {
        // fused QKV epilogue.  N window type within the 384-col head block:
        const int type = (nBase >> 7) % 3;     // 0=q, 1=k, 2=v
        const int h = nBase / 384;
        const bool rot = (wn == 0) && (type < 2);  // cols [0,32) of q/k: RoPE
        float invf[4];
        if (rot) {
            const float cexp = 9.210340371976184f / 16.0f;  // ln(10000)/16
            invf[0] = expf(-(float)(t2)     * cexp);
            invf[1] = expf(-(float)(t2 + 1) * cexp);
            invf[2] = expf(-(float)(t2 + 8) * cexp);
            invf[3] = expf(-(float)(t2 + 9) * cexp);
        }
        __half* outp = (type == 0) ? qout : ((type == 1) ? kout : vout);
        const float sc = (type == 0) ? 0.08838834764831843f : 1.0f;
#pragma unroll
        for (int mi = 0; mi < 4; mi++) {
#pragma unroll
            for (int rr = 0; rr < 2; rr++) {
                int row = mBase + wm * 64 + mi * 16 + qrow + rr * 8;
                int b = row >> 11, s = row & 2047;
                float vals[8];
#pragma unroll
                for (int ni = 0; ni < 4; ni++) {
                    int col = nBase + wn * 32 + ni * 8 + t2;
                    vals[2 * ni]     = acc[mi][ni][2 * rr]     + bias[col];
                    vals[2 * ni + 1] = acc[mi][ni][2 * rr + 1] + bias[col + 1];
                }
                if (rot) {
                    // pairs: vals[j]<->vals[4+j] (freq t2+j), vals[2+j]<->vals[6+j] (freq 8+t2+j)
                    float sn, cs;
#pragma unroll
                    for (int j = 0; j < 2; j++) {
                        sincosf((float)s * invf[j], &sn, &cs);
                        float lo = vals[j], hi = vals[4 + j];
                        vals[j]     = lo * cs - hi * sn;
                        vals[4 + j] = hi * cs + lo * sn;
                        sincosf((float)s * invf[2 + j], &sn, &cs);
                        float lo2 = vals[2 + j], hi2 = vals[6 + j];
                        vals[2 + j] = lo2 * cs - hi2 * sn;
                        vals[6 + j] = hi2 * cs + lo2 * sn;
                    }
                }
                size_t ob = ((size_t)(b * 16 + h) * SEQ + s) * 128 + wn * 32 + t2;
#pragma unroll
                for (int ni = 0; ni < 4; ni++) {
                    __half2 hv = __floats2half2_rn(vals[2 * ni] * sc,
                                                   vals[2 * ni + 1] * sc);
                    *(__half2*)(outp + ob + ni * 8) = hv;
                }
            }
        }
    }
}

// ---------------------------------------------------------------------------
// Flash attention via mma.sync, single fp16 (Q,K,P,V), causal, no-max softmax.
// BQ=128 (8 warps x 16 rows), BKV=64, D=128.
// Q resident (34816B); KV stages 34816B each.  Output written pre-split
// (fp16 hi/lo) into g_ah/g_al for the out-proj.
// ---------------------------------------------------------------------------
#define FKV 34816
#define FL_SMEM (34816 + 2 * FKV)

__global__ __launch_bounds__(256, 1)
void flash_mma(const __half* __restrict__ qhp, const __half* __restrict__ khp,
               const __half* __restrict__ vhp,
               __half* __restrict__ oh, __half* __restrict__ ol)
{
    extern __shared__ __align__(16) char smem[];
    const int tid = threadIdx.x, lane = tid & 31, warp = tid >> 5;
    const int qi = 15 - (int)blockIdx.x;        // heavy q-tiles first
    const int bh = blockIdx.y;
    const int q0 = qi << 7;
    const int nkv = 2 * qi + 2;
    u32 sb = (u32)__cvta_generic_to_shared(smem);

    const int g = lane >> 3, rsel = lane & 7;
    const size_t base = (size_t)bh * SEQ * 128;

    // ---- Q loads (resident @0) ----
#pragma unroll
    for (int i = 0; i < 8; i++) {
        int idx = i * 256 + tid;                 // 0..2047
        int row = idx >> 4, c = idx & 15;
        cpa16(sb + (u32)(row * 272 + c * 16),
              qhp + base + (size_t)(q0 + row) * 128 + c * 8);
    }
    asm volatile("cp.async.commit_group;" ::: "memory");

    auto load_kv = [&](int kt) {
        u32 st = sb + (u32)(34816 + (kt & 1) * FKV);
        const size_t rb = base + (size_t)(kt * 64) * 128;
#pragma unroll
        for (int i = 0; i < 2; i++) {
            int idx = i * 256 + tid;             // 0..511
            int row = idx >> 3, c = idx & 7;     // 64 rows x 8 chunks of 16 cols
            u32 d = st + (u32)(row * 272 + c * 32);
            size_t s = rb + (size_t)row * 128 + c * 16;
            cpa16(d,          khp + s);
            cpa16(d + 16,     khp + s + 8);
            cpa16(d + 17408,      vhp + s);
            cpa16(d + 17408 + 16, vhp + s + 8);
        }
        asm volatile("cp.async.commit_group;" ::: "memory");
    };

    load_kv(0);

    float oacc[16][4];
#pragma unroll
    for (int i = 0; i < 16; i++)
#pragma unroll
        for (int j = 0; j < 4; j++) oacc[i][j] = 0.f;
    float lsum0 = 0.f, lsum1 = 0.f;

    const u32 qoff = sb + (u32)((warp * 16 + (g & 1) * 8 + rsel) * 272 + (g >> 1) * 16);
    const int rowq = warp * 16 + (lane >> 2);        // local q row (of pair)

    for (int kt = 0; kt < nkv; kt++) {
        asm volatile("cp.async.wait_group 0;" ::: "memory");
        __syncthreads();
        if (kt + 1 < nkv) load_kv(kt + 1);
        u32 st = sb + (u32)(34816 + (kt & 1) * FKV);

        // ---- S = Q K^T  (single fp16) ----
        float sacc[8][4];
#pragma unroll
        for (int i = 0; i < 8; i++)
#pragma unroll
            for (int j = 0; j < 4; j++) sacc[i][j] = 0.f;

        const u32 kb = st + (u32)(((g >> 1) * 8 + rsel) * 272 + (g & 1) * 16);
#pragma unroll
        for (int ks = 0; ks < 8; ks++) {
            u32 qh4[4];
            ldsm4(qh4, qoff + ks * 32);
            u32 tb[4][4];
#pragma unroll
            for (int ng = 0; ng < 4; ng++)
                ldsm4(tb[ng], kb + ng * (16 * 272) + ks * 32);
#pragma unroll
            for (int ng = 0; ng < 4; ng++) {
                mma_f16(sacc[2 * ng],     qh4, tb[ng]);
                mma_f16(sacc[2 * ng + 1], qh4, tb[ng] + 2);
            }
        }

        // ---- softmax numerator (no max-subtraction; scores are O(1)) ----
        const bool diag = (kt >= 2 * qi);
        const int row0 = q0 + rowq;
        const int colb = kt * 64 + 2 * (lane & 3);
        u32 pah[4][4];
#pragma unroll
        for (int ni = 0; ni < 8; ni++) {
            int c0 = colb + ni * 8;
            float p0, p1, p2, p3;
            if (diag) {
                p0 = (c0     <= row0    ) ? fexp(sacc[ni][0]) : 0.f;
                p1 = (c0 + 1 <= row0    ) ? fexp(sacc[ni][1]) : 0.f;
                p2 = (c0     <= row0 + 8) ? fexp(sacc[ni][2]) : 0.f;
                p3 = (c0 + 1 <= row0 + 8) ? fexp(sacc[ni][3]) : 0.f;
            } else {
                p0 = fexp(sacc[ni][0]); p1 = fexp(sacc[ni][1]);
                p2 = fexp(sacc[ni][2]); p3 = fexp(sacc[ni][3]);
            }
            lsum0 += p0 + p1;
            lsum1 += p2 + p3;
            int kt2 = ni >> 1, j = (ni & 1) * 2;
            __half2 h0 = __floats2half2_rn(p0, p1);
            __half2 h1 = __floats2half2_rn(p2, p3);
            pah[kt2][j]     = *(u32*)&h0;
            pah[kt2][j + 1] = *(u32*)&h1;
        }

        // ---- O += P V  (single fp16, V via trans ldmatrix) ----
        const u32 vb = st + 17408 + (u32)(((g & 1) * 8 + rsel) * 272 + (g >> 1) * 16);
#pragma unroll
        for (int kt2 = 0; kt2 < 4; kt2++) {
#pragma unroll
            for (int dgp = 0; dgp < 4; dgp++) {
                u32 th0[4], th1[4];
                u32 vbb = vb + kt2 * (16 * 272) + dgp * 64;
                ldsm4t(th0, vbb);
                ldsm4t(th1, vbb + 32);
                mma_f16(oacc[4 * dgp],     pah[kt2], th0);
                mma_f16(oacc[4 * dgp + 1], pah[kt2], th0 + 2);
                mma_f16(oacc[4 * dgp + 2], pah[kt2], th1);
                mma_f16(oacc[4 * dgp + 3], pah[kt2], th1 + 2);
            }
        }
    }

    // ---- normalize + pre-split store into g_ah/g_al ----
    lsum0 += __shfl_xor_sync(0xffffffffu, lsum0, 1);
    lsum0 += __shfl_xor_sync(0xffffffffu, lsum0, 2);
    lsum1 += __shfl_xor_sync(0xffffffffu, lsum1, 1);
    lsum1 += __shfl_xor_sync(0xffffffffu, lsum1, 2);
    float inv0 = 1.f / lsum0, inv1 = 1.f / lsum1;

    const int b = bh >> 4, h = bh & 15;
    const int r0 = q0 + rowq;
    size_t obase0 = ((size_t)(b * SEQ + r0)) * HID + h * 128;
    size_t obase1 = obase0 + (size_t)8 * HID;
#pragma unroll
    for (int dt = 0; dt < 16; dt++) {
        int col = dt * 8 + 2 * (lane & 3);
        u32 hi0, lo0, hi1, lo1;
        split2h(oacc[dt][0] * inv0, oacc[dt][1] * inv0, hi0, lo0);
        split2h(oacc[dt][2] * inv1, oacc[dt][3] * inv1, hi1, lo1);
        *(u32*)(oh + obase0 + col) = hi0;
        *(u32*)(ol + obase0 + col) = lo0;
        *(u32*)(oh + obase1 + col) = hi1;
        *(u32*)(ol + obase1 + col) = lo1;
    }
}

// ---------------------------------------------------------------------------
extern "C" void kernel_launch(void* const* d_in, const int* in_sizes, int n_in,
                              void* d_out, int out_size)
{
    const float* hidden = (const float*)d_in[0];
    const float* qkvk = (const float*)d_in[2];
    const float* qkvb = (const float*)d_in[3];
    const float* outk = (const float*)d_in[4];
    const float* outb = (const float*)d_in[5];
    float* out = (float*)d_out;

    __half *pqh, *pkh, *pvh, *pah, *pal, *pbh;
    cudaGetSymbolAddress((void**)&pqh, g_qh);
    cudaGetSymbolAddress((void**)&pkh, g_kh);
    cudaGetSymbolAddress((void**)&pvh, g_vh);
    cudaGetSymbolAddress((void**)&pah, g_ah);
    cudaGetSymbolAddress((void**)&pal, g_al);
    cudaGetSymbolAddress((void**)&pbh, g_bh);

    cudaFuncSetAttribute((const void*)gemm_mma,
                         cudaFuncAttributeMaxDynamicSharedMemorySize, 3 * GST);
    cudaFuncSetAttribute((const void*)flash_mma,
                         cudaFuncAttributeMaxDynamicSharedMemorySize, FL_SMEM);

    // --- QKV projection + fused RoPE/fp16 epilogue ---
    split_rm<<<(4096 * 2048 / 4 + 255) / 256, 256>>>((const float4*)hidden, pah, pal, 4096 * 2048 / 4);
    tsplit<<<dim3(6144 / 32, 2048 / 32), dim3(32, 8)>>>(qkvk, pbh, 2048, 6144);
    gemm_mma<<<dim3(48, 32), 256, 3 * GST>>>(pah, pal, pbh, qkvb, nullptr,
                                             4096, 6144, 2048, 1, pqh, pkh, pvh);

    // --- causal flash attention (single-fp16 HMMA), writes pre-split out-proj A ---
    flash_mma<<<dim3(16, 32), 256, FL_SMEM>>>(pqh, pkh, pvh, pah, pal);

    // --- output projection: [4096,2048] @ [2048,2048] + bias ---
    tsplit<<<dim3(2048 / 32, 2048 / 32), dim3(32, 8)>>>(outk, pbh, 2048, 2048);
    gemm_mma<<<dim3(16, 32), 256, 3 * GST>>>(pah, pal, pbh, outb, out,
                                             4096, 2048, 2048, 0, nullptr, nullptr, nullptr);
}

// round 15
// speedup vs baseline: 6.5216x; 1.7613x over previous
#include <cuda_runtime.h>
#include <cuda_fp16.h>
#include <math.h>
#include <stdint.h>

#define SEQ    2048
#define NQKV   6144
#define HID    2048

typedef unsigned long long u64;
typedef unsigned int u32;

// ------------------------- scratch (device globals) -------------------------
__device__ __half g_qh[(size_t)32 * SEQ * 128];       // Q single (pre-scaled) [bh][s][d]
__device__ __half g_kh[(size_t)32 * SEQ * 128];       // K single
__device__ __half g_vh[(size_t)32 * SEQ * 128];       // V single
__device__ __half g_ah[(size_t)4096 * 2048];          // A single [M][K] (activations)
__device__ __half g_bh[(size_t)6144 * 2048];          // B^T single [N][K] (weights)

// ------------------------- async / mma helpers (base PTX only) ---------------
__device__ __forceinline__ void cpa16(u32 dst, const void* src) {
    asm volatile("cp.async.cg.shared.global [%0], [%1], 16;" :: "r"(dst), "l"(src));
}
__device__ __forceinline__ void ldsm4(u32 r[4], u32 addr) {
    asm volatile("ldmatrix.sync.aligned.m8n8.x4.shared.b16 {%0,%1,%2,%3}, [%4];"
                 : "=r"(r[0]), "=r"(r[1]), "=r"(r[2]), "=r"(r[3]) : "r"(addr));
}
__device__ __forceinline__ void ldsm4t(u32 r[4], u32 addr) {
    asm volatile("ldmatrix.sync.aligned.m8n8.x4.trans.shared.b16 {%0,%1,%2,%3}, [%4];"
                 : "=r"(r[0]), "=r"(r[1]), "=r"(r[2]), "=r"(r[3]) : "r"(addr));
}
__device__ __forceinline__ void mma_f16(float c[4], const u32 a[4], const u32 b[2]) {
    asm volatile("mma.sync.aligned.m16n8k16.row.col.f32.f16.f16.f32 "
                 "{%0,%1,%2,%3}, {%4,%5,%6,%7}, {%8,%9}, {%0,%1,%2,%3};"
                 : "+f"(c[0]), "+f"(c[1]), "+f"(c[2]), "+f"(c[3])
                 : "r"(a[0]), "r"(a[1]), "r"(a[2]), "r"(a[3]), "r"(b[0]), "r"(b[1]));
}

// fast exp on the FMA pipe (rel err ~2.4e-6)
__device__ __forceinline__ float fexp(float x) {
    float t = fmaxf(x, -80.f) * 1.4426950408889634f;
    float z = t + 12582912.f;
    int e = __float_as_int(z) - 0x4B400000;
    float f = t - (z - 12582912.f);
    float g = f * 0.6931471805599453f;
    float r = fmaf(g, 0.0083333333f, 0.0416666667f);
    r = fmaf(g, r, 0.16666667f);
    r = fmaf(g, r, 0.5f);
    r = fmaf(g, r, 1.0f);
    r = fmaf(g, r, 1.0f);
    return r * __int_as_float((e + 127) << 23);
}

// ---------------------------------------------------------------------------
// fp32 -> fp16 convert (row-major activations)
// ---------------------------------------------------------------------------
__global__ void conv_rm(const float4* __restrict__ x, __half* __restrict__ hi, int n4)
{
    int i = blockIdx.x * 256 + threadIdx.x;
    if (i >= n4) return;
    float4 v = x[i];
    __half2 a = __floats2half2_rn(v.x, v.y);
    __half2 b = __floats2half2_rn(v.z, v.w);
    *(uint2*)(hi + 4 * (size_t)i) = make_uint2(*(u32*)&a, *(u32*)&b);
}

// W [K][N] row-major -> single fp16 [N][K]  (tiled smem transpose)
__global__ void tsplit(const float* __restrict__ w, __half* __restrict__ hi,
                       int K, int N)
{
    __shared__ float t[32][33];
    const int k0 = blockIdx.y << 5, n0 = blockIdx.x << 5;
    const int tx = threadIdx.x, ty = threadIdx.y;   // 32 x 8
#pragma unroll
    for (int i = 0; i < 4; i++)
        t[ty + 8 * i][tx] = w[(size_t)(k0 + ty + 8 * i) * N + n0 + tx];
    __syncthreads();
#pragma unroll
    for (int i = 0; i < 4; i++)
        hi[(size_t)(n0 + ty + 8 * i) * K + k0 + tx] = __float2half(t[tx][ty + 8 * i]);
}

// ---------------------------------------------------------------------------
// fp16 GEMM via mma.sync:  C[M,N] = A[M,K] @ B^T[N,K]^T + bias[N]
// Single fp16 both operands.  128x128 tile, BK=32, 8 warps, 3-stage ring,
// 2 CTAs/SM (60KB smem, <=128 regs via launch bounds).
// mode 0: fp32 C store.   mode 1: fused QKV epilogue (RoPE + fp16 scatter).
// ---------------------------------------------------------------------------
#define GST 20480   // A 10240 | B 10240

__global__ __launch_bounds__(256, 2)
void gemm_mma(const __half* __restrict__ Ahp, const __half* __restrict__ Bhp,
              const float* __restrict__ bias, float* __restrict__ C,
              int M, int N, int K, int mode,
              __half* __restrict__ qout, __half* __restrict__ kout,
              __half* __restrict__ vout)
{
    extern __shared__ __align__(16) char smem[];
    const int tid = threadIdx.x, lane = tid & 31, warp = tid >> 5;
    const int wm = warp & 1, wn = warp >> 1;
    const int mBase = blockIdx.y * 128, nBase = blockIdx.x * 128;
    u32 sb = (u32)__cvta_generic_to_shared(smem);

    const int g = lane >> 3, rsel = lane & 7;
    const u32 offA = (u32)((wm * 64 + (g & 1) * 8 + rsel) * 80 + (g >> 1) * 16);
    const u32 offB = (u32)((wn * 32 + (g >> 1) * 8 + rsel) * 80 + (g & 1) * 16);

    float acc[4][4][4];
#pragma unroll
    for (int a = 0; a < 4; a++)
#pragma unroll
        for (int b = 0; b < 4; b++)
#pragma unroll
            for (int c = 0; c < 4; c++) acc[a][b][c] = 0.f;

    const int niter = K >> 5;

    auto load_stage = [&](int stage, int kc) {
        u32 st = sb + (u32)stage * GST;
#pragma unroll
        for (int i = 0; i < 2; i++) {
            int ch = i * 256 + tid;              // 0..511
            int row = ch >> 2, c = ch & 3;
            u32 d = st + (u32)(row * 80 + c * 16);
            cpa16(d,         Ahp + (size_t)(mBase + row) * K + kc * 32 + c * 8);
            cpa16(d + 10240, Bhp + (size_t)(nBase + row) * K + kc * 32 + c * 8);
        }
        asm volatile("cp.async.commit_group;" ::: "memory");
    };

    load_stage(0, 0);
    load_stage(1, 1);

    for (int it = 0; it < niter; it++) {
        if (it + 1 < niter) {
            asm volatile("cp.async.wait_group 1;" ::: "memory");
        } else {
            asm volatile("cp.async.wait_group 0;" ::: "memory");
        }
        __syncthreads();
        if (it + 2 < niter) load_stage((it + 2) % 3, it + 2);

        u32 st = sb + (u32)(it % 3) * GST;
#pragma unroll
        for (int ks = 0; ks < 2; ks++) {
            u32 ah[4][4], bh[4][2];
#pragma unroll
            for (int mi = 0; mi < 4; mi++)
                ldsm4(ah[mi], st + offA + (u32)(mi * 16 * 80 + ks * 32));
#pragma unroll
            for (int nh = 0; nh < 2; nh++) {
                u32 t[4];
                ldsm4(t, st + 10240 + offB + (u32)(nh * 16 * 80 + ks * 32));
                bh[2 * nh][0] = t[0]; bh[2 * nh][1] = t[1];
                bh[2 * nh + 1][0] = t[2]; bh[2 * nh + 1][1] = t[3];
            }
#pragma unroll
            for (int mi = 0; mi < 4; mi++)
#pragma unroll
                for (int ni = 0; ni < 4; ni++)
                    mma_f16(acc[mi][ni], ah[mi], bh[ni]);
        }
    }

    __syncthreads();
    const int qrow = lane >> 2, t2 = (lane & 3) * 2;

    if (mode == 0) {
#pragma unroll
        for (int mi = 0; mi < 4; mi++) {
            int r0 = mBase + wm * 64 + mi * 16 + qrow;
#pragma unroll
            for (int ni = 0; ni < 4; ni++) {
                int col = nBase + wn * 32 + ni * 8 + t2;
                float b0 = bias[col], b1 = bias[col + 1];
                *(float2*)&C[(size_t)r0 * N + col] =
                    make_float2(acc[mi][ni][0] + b0, acc[mi][ni][1] + b1);
                *(float2*)&C[(size_t)(r0 + 8) * N + col] =
                    make_float2(acc[mi][ni][2] + b0, acc[mi][ni][3] + b1);
            }
        }
    } else {
        // fused QKV epilogue.  N window type within the 384-col head block:
        const int type = (nBase >> 7) % 3;     // 0=q, 1=k, 2=v
        const int h = nBase / 384;
        const bool rot = (wn == 0) && (type < 2);  // cols [0,32) of q/k: RoPE
        float invf[4];
        if (rot) {
            const float cexp = 9.210340371976184f / 16.0f;  // ln(10000)/16
            invf[0] = expf(-(float)(t2)     * cexp);
            invf[1] = expf(-(float)(t2 + 1) * cexp);
            invf[2] = expf(-(float)(t2 + 8) * cexp);
            invf[3] = expf(-(float)(t2 + 9) * cexp);
        }
        __half* outp = (type == 0) ? qout : ((type == 1) ? kout : vout);
        const float sc = (type == 0) ? 0.08838834764831843f : 1.0f;
#pragma unroll
        for (int mi = 0; mi < 4; mi++) {
#pragma unroll
            for (int rr = 0; rr < 2; rr++) {
                int row = mBase + wm * 64 + mi * 16 + qrow + rr * 8;
                int b = row >> 11, s = row & 2047;
                float vals[8];
#pragma unroll
                for (int ni = 0; ni < 4; ni++) {
                    int col = nBase + wn * 32 + ni * 8 + t2;
                    vals[2 * ni]     = acc[mi][ni][2 * rr]     + bias[col];
                    vals[2 * ni + 1] = acc[mi][ni][2 * rr + 1] + bias[col + 1];
                }
                if (rot) {
                    float sn, cs;
#pragma unroll
                    for (int j = 0; j < 2; j++) {
                        sincosf((float)s * invf[j], &sn, &cs);
                        float lo = vals[j], hi = vals[4 + j];
                        vals[j]     = lo * cs - hi * sn;
                        vals[4 + j] = hi * cs + lo * sn;
                        sincosf((float)s * invf[2 + j], &sn, &cs);
                        float lo2 = vals[2 + j], hi2 = vals[6 + j];
                        vals[2 + j] = lo2 * cs - hi2 * sn;
                        vals[6 + j] = hi2 * cs + lo2 * sn;
                    }
                }
                size_t ob = ((size_t)(b * 16 + h) * SEQ + s) * 128 + wn * 32 + t2;
#pragma unroll
                for (int ni = 0; ni < 4; ni++) {
                    __half2 hv = __floats2half2_rn(vals[2 * ni] * sc,
                                                   vals[2 * ni + 1] * sc);
                    *(__half2*)(outp + ob + ni * 8) = hv;
                }
            }
        }
    }
}

// ---------------------------------------------------------------------------
// Flash attention via mma.sync, single fp16 (Q,K,P,V), causal, no-max softmax.
// BQ=128 (8 warps x 16 rows), BKV=64, D=128.
// Q resident (34816B); KV stages 34816B each.  Output written single fp16
// into g_ah (out-proj A operand), [b*s][2048].
// ---------------------------------------------------------------------------
#define FKV 34816
#define FL_SMEM (34816 + 2 * FKV)

__global__ __launch_bounds__(256, 1)
void flash_mma(const __half* __restrict__ qhp, const __half* __restrict__ khp,
               const __half* __restrict__ vhp, __half* __restrict__ oh)
{
    extern __shared__ __align__(16) char smem[];
    const int tid = threadIdx.x, lane = tid & 31, warp = tid >> 5;
    const int qi = 15 - (int)blockIdx.x;        // heavy q-tiles first
    const int bh = blockIdx.y;
    const int q0 = qi << 7;
    const int nkv = 2 * qi + 2;
    u32 sb = (u32)__cvta_generic_to_shared(smem);

    const int g = lane >> 3, rsel = lane & 7;
    const size_t base = (size_t)bh * SEQ * 128;

    // ---- Q loads (resident @0) ----
#pragma unroll
    for (int i = 0; i < 8; i++) {
        int idx = i * 256 + tid;                 // 0..2047
        int row = idx >> 4, c = idx & 15;
        cpa16(sb + (u32)(row * 272 + c * 16),
              qhp + base + (size_t)(q0 + row) * 128 + c * 8);
    }
    asm volatile("cp.async.commit_group;" ::: "memory");

    auto load_kv = [&](int kt) {
        u32 st = sb + (u32)(34816 + (kt & 1) * FKV);
        const size_t rb = base + (size_t)(kt * 64) * 128;
#pragma unroll
        for (int i = 0; i < 2; i++) {
            int idx = i * 256 + tid;             // 0..511
            int row = idx >> 3, c = idx & 7;     // 64 rows x 8 chunks of 16 cols
            u32 d = st + (u32)(row * 272 + c * 32);
            size_t s = rb + (size_t)row * 128 + c * 16;
            cpa16(d,          khp + s);
            cpa16(d + 16,     khp + s + 8);
            cpa16(d + 17408,      vhp + s);
            cpa16(d + 17408 + 16, vhp + s + 8);
        }
        asm volatile("cp.async.commit_group;" ::: "memory");
    };

    load_kv(0);

    float oacc[16][4];
#pragma unroll
    for (int i = 0; i < 16; i++)
#pragma unroll
        for (int j = 0; j < 4; j++) oacc[i][j] = 0.f;
    float lsum0 = 0.f, lsum1 = 0.f;

    const u32 qoff = sb + (u32)((warp * 16 + (g & 1) * 8 + rsel) * 272 + (g >> 1) * 16);
    const int rowq = warp * 16 + (lane >> 2);        // local q row (of pair)

    for (int kt = 0; kt < nkv; kt++) {
        asm volatile("cp.async.wait_group 0;" ::: "memory");
        __syncthreads();
        if (kt + 1 < nkv) load_kv(kt + 1);
        u32 st = sb + (u32)(34816 + (kt & 1) * FKV);

        // ---- S = Q K^T  (single fp16) ----
        float sacc[8][4];
#pragma unroll
        for (int i = 0; i < 8; i++)
#pragma unroll
            for (int j = 0; j < 4; j++) sacc[i][j] = 0.f;

        const u32 kb = st + (u32)(((g >> 1) * 8 + rsel) * 272 + (g & 1) * 16);
#pragma unroll
        for (int ks = 0; ks < 8; ks++) {
            u32 qh4[4];
            ldsm4(qh4, qoff + ks * 32);
            u32 tb[4][4];
#pragma unroll
            for (int ng = 0; ng < 4; ng++)
                ldsm4(tb[ng], kb + ng * (16 * 272) + ks * 32);
#pragma unroll
            for (int ng = 0; ng < 4; ng++) {
                mma_f16(sacc[2 * ng],     qh4, tb[ng]);
                mma_f16(sacc[2 * ng + 1], qh4, tb[ng] + 2);
            }
        }

        // ---- softmax numerator (no max-subtraction; scores are O(1)) ----
        const bool diag = (kt >= 2 * qi);
        const int row0 = q0 + rowq;
        const int colb = kt * 64 + 2 * (lane & 3);
        u32 pah[4][4];
#pragma unroll
        for (int ni = 0; ni < 8; ni++) {
            int c0 = colb + ni * 8;
            float p0, p1, p2, p3;
            if (diag) {
                p0 = (c0     <= row0    ) ? fexp(sacc[ni][0]) : 0.f;
                p1 = (c0 + 1 <= row0    ) ? fexp(sacc[ni][1]) : 0.f;
                p2 = (c0     <= row0 + 8) ? fexp(sacc[ni][2]) : 0.f;
                p3 = (c0 + 1 <= row0 + 8) ? fexp(sacc[ni][3]) : 0.f;
            } else {
                p0 = fexp(sacc[ni][0]); p1 = fexp(sacc[ni][1]);
                p2 = fexp(sacc[ni][2]); p3 = fexp(sacc[ni][3]);
            }
            lsum0 += p0 + p1;
            lsum1 += p2 + p3;
            int kt2 = ni >> 1, j = (ni & 1) * 2;
            __half2 h0 = __floats2half2_rn(p0, p1);
            __half2 h1 = __floats2half2_rn(p2, p3);
            pah[kt2][j]     = *(u32*)&h0;
            pah[kt2][j + 1] = *(u32*)&h1;
        }

        // ---- O += P V  (single fp16, V via trans ldmatrix) ----
        const u32 vb = st + 17408 + (u32)(((g & 1) * 8 + rsel) * 272 + (g >> 1) * 16);
#pragma unroll
        for (int kt2 = 0; kt2 < 4; kt2++) {
#pragma unroll
            for (int dgp = 0; dgp < 4; dgp++) {
                u32 th0[4], th1[4];
                u32 vbb = vb + kt2 * (16 * 272) + dgp * 64;
                ldsm4t(th0, vbb);
                ldsm4t(th1, vbb + 32);
                mma_f16(oacc[4 * dgp],     pah[kt2], th0);
                mma_f16(oacc[4 * dgp + 1], pah[kt2], th0 + 2);
                mma_f16(oacc[4 * dgp + 2], pah[kt2], th1);
                mma_f16(oacc[4 * dgp + 3], pah[kt2], th1 + 2);
            }
        }
    }

    // ---- normalize + fp16 store into g_ah (out-proj A) ----
    lsum0 += __shfl_xor_sync(0xffffffffu, lsum0, 1);
    lsum0 += __shfl_xor_sync(0xffffffffu, lsum0, 2);
    lsum1 += __shfl_xor_sync(0xffffffffu, lsum1, 1);
    lsum1 += __shfl_xor_sync(0xffffffffu, lsum1, 2);
    float inv0 = 1.f / lsum0, inv1 = 1.f / lsum1;

    const int b = bh >> 4, h = bh & 15;
    const int r0 = q0 + rowq;
    size_t obase0 = ((size_t)(b * SEQ + r0)) * HID + h * 128;
    size_t obase1 = obase0 + (size_t)8 * HID;
#pragma unroll
    for (int dt = 0; dt < 16; dt++) {
        int col = dt * 8 + 2 * (lane & 3);
        __half2 h0 = __floats2half2_rn(oacc[dt][0] * inv0, oacc[dt][1] * inv0);
        __half2 h1 = __floats2half2_rn(oacc[dt][2] * inv1, oacc[dt][3] * inv1);
        *(u32*)(oh + obase0 + col) = *(u32*)&h0;
        *(u32*)(oh + obase1 + col) = *(u32*)&h1;
    }
}

// ---------------------------------------------------------------------------
extern "C" void kernel_launch(void* const* d_in, const int* in_sizes, int n_in,
                              void* d_out, int out_size)
{
    const float* hidden = (const float*)d_in[0];
    const float* qkvk = (const float*)d_in[2];
    const float* qkvb = (const float*)d_in[3];
    const float* outk = (const float*)d_in[4];
    const float* outb = (const float*)d_in[5];
    float* out = (float*)d_out;

    __half *pqh, *pkh, *pvh, *pah, *pbh;
    cudaGetSymbolAddress((void**)&pqh, g_qh);
    cudaGetSymbolAddress((void**)&pkh, g_kh);
    cudaGetSymbolAddress((void**)&pvh, g_vh);
    cudaGetSymbolAddress((void**)&pah, g_ah);
    cudaGetSymbolAddress((void**)&pbh, g_bh);

    cudaFuncSetAttribute((const void*)gemm_mma,
                         cudaFuncAttributeMaxDynamicSharedMemorySize, 3 * GST);
    cudaFuncSetAttribute((const void*)flash_mma,
                         cudaFuncAttributeMaxDynamicSharedMemorySize, FL_SMEM);

    // --- QKV projection + fused RoPE/fp16 epilogue ---
    conv_rm<<<(4096 * 2048 / 4 + 255) / 256, 256>>>((const float4*)hidden, pah, 4096 * 2048 / 4);
    tsplit<<<dim3(6144 / 32, 2048 / 32), dim3(32, 8)>>>(qkvk, pbh, 2048, 6144);
    gemm_mma<<<dim3(48, 32), 256, 3 * GST>>>(pah, pbh, qkvb, nullptr,
                                             4096, 6144, 2048, 1, pqh, pkh, pvh);

    // --- causal flash attention (single-fp16 HMMA), writes out-proj A ---
    flash_mma<<<dim3(16, 32), 256, FL_SMEM>>>(pqh, pkh, pvh, pah);

    // --- output projection: [4096,2048] @ [2048,2048] + bias ---
    tsplit<<<dim3(2048 / 32, 2048 / 32), dim3(32, 8)>>>(outk, pbh, 2048, 2048);
    gemm_mma<<<dim3(16, 32), 256, 3 * GST>>>(pah, pbh, outb, out,
                                             4096, 2048, 2048, 0, nullptr, nullptr, nullptr);
}

// round 16
// speedup vs baseline: 6.6322x; 1.0170x over previous
#include <cuda_runtime.h>
#include <cuda_fp16.h>
#include <math.h>
#include <stdint.h>

#define SEQ    2048
#define NQKV   6144
#define HID    2048

typedef unsigned long long u64;
typedef unsigned int u32;

// ------------------------- scratch (device globals) -------------------------
__device__ __half g_qh[(size_t)32 * SEQ * 128];       // Q single (pre-scaled) [bh][s][d]
__device__ __half g_kh[(size_t)32 * SEQ * 128];       // K single
__device__ __half g_vh[(size_t)32 * SEQ * 128];       // V single
__device__ __half g_ah[(size_t)4096 * 2048];          // A single [M][K] (activations)
__device__ __half g_bh[(size_t)6144 * 2048];          // B^T single [N][K] (weights)

// ------------------------- async / mma helpers (base PTX only) ---------------
__device__ __forceinline__ void cpa16(u32 dst, const void* src) {
    asm volatile("cp.async.cg.shared.global [%0], [%1], 16;" :: "r"(dst), "l"(src));
}
__device__ __forceinline__ void ldsm4(u32 r[4], u32 addr) {
    asm volatile("ldmatrix.sync.aligned.m8n8.x4.shared.b16 {%0,%1,%2,%3}, [%4];"
                 : "=r"(r[0]), "=r"(r[1]), "=r"(r[2]), "=r"(r[3]) : "r"(addr));
}
__device__ __forceinline__ void ldsm4t(u32 r[4], u32 addr) {
    asm volatile("ldmatrix.sync.aligned.m8n8.x4.trans.shared.b16 {%0,%1,%2,%3}, [%4];"
                 : "=r"(r[0]), "=r"(r[1]), "=r"(r[2]), "=r"(r[3]) : "r"(addr));
}
__device__ __forceinline__ void mma_f16(float c[4], const u32 a[4], const u32 b[2]) {
    asm volatile("mma.sync.aligned.m16n8k16.row.col.f32.f16.f16.f32 "
                 "{%0,%1,%2,%3}, {%4,%5,%6,%7}, {%8,%9}, {%0,%1,%2,%3};"
                 : "+f"(c[0]), "+f"(c[1]), "+f"(c[2]), "+f"(c[3])
                 : "r"(a[0]), "r"(a[1]), "r"(a[2]), "r"(a[3]), "r"(b[0]), "r"(b[1]));
}

// fast exp on the FMA pipe (rel err ~2.4e-6)
__device__ __forceinline__ float fexp(float x) {
    float t = fmaxf(x, -80.f) * 1.4426950408889634f;
    float z = t + 12582912.f;
    int e = __float_as_int(z) - 0x4B400000;
    float f = t - (z - 12582912.f);
    float g = f * 0.6931471805599453f;
    float r = fmaf(g, 0.0083333333f, 0.0416666667f);
    r = fmaf(g, r, 0.16666667f);
    r = fmaf(g, r, 0.5f);
    r = fmaf(g, r, 1.0f);
    r = fmaf(g, r, 1.0f);
    return r * __int_as_float((e + 127) << 23);
}

// ---------------------------------------------------------------------------
// fp32 -> fp16 convert (row-major activations)
// ---------------------------------------------------------------------------
__global__ void conv_rm(const float4* __restrict__ x, __half* __restrict__ hi, int n4)
{
    int i = blockIdx.x * 256 + threadIdx.x;
    if (i >= n4) return;
    float4 v = x[i];
    __half2 a = __floats2half2_rn(v.x, v.y);
    __half2 b = __floats2half2_rn(v.z, v.w);
    *(uint2*)(hi + 4 * (size_t)i) = make_uint2(*(u32*)&a, *(u32*)&b);
}

// W [K][N] row-major -> single fp16 [N][K]  (tiled smem transpose)
__global__ void tsplit(const float* __restrict__ w, __half* __restrict__ hi,
                       int K, int N)
{
    __shared__ float t[32][33];
    const int k0 = blockIdx.y << 5, n0 = blockIdx.x << 5;
    const int tx = threadIdx.x, ty = threadIdx.y;   // 32 x 8
#pragma unroll
    for (int i = 0; i < 4; i++)
        t[ty + 8 * i][tx] = w[(size_t)(k0 + ty + 8 * i) * N + n0 + tx];
    __syncthreads();
#pragma unroll
    for (int i = 0; i < 4; i++)
        hi[(size_t)(n0 + ty + 8 * i) * K + k0 + tx] = __float2half(t[tx][ty + 8 * i]);
}

// ---------------------------------------------------------------------------
// fp16 GEMM via mma.sync:  C[M,N] = A[M,K] @ B^T[N,K]^T + bias[N]
// Single fp16 both operands.  128x128 tile, BK=32, 8 warps, 3-stage ring,
// 2 CTAs/SM.  mode 0: fp32 C store.  mode 1: fused QKV epilogue.
// ---------------------------------------------------------------------------
#define GST 20480   // A 10240 | B 10240

__global__ __launch_bounds__(256, 2)
void gemm_mma(const __half* __restrict__ Ahp, const __half* __restrict__ Bhp,
              const float* __restrict__ bias, float* __restrict__ C,
              int M, int N, int K, int mode,
              __half* __restrict__ qout, __half* __restrict__ kout,
              __half* __restrict__ vout)
{
    extern __shared__ __align__(16) char smem[];
    const int tid = threadIdx.x, lane = tid & 31, warp = tid >> 5;
    const int wm = warp & 1, wn = warp >> 1;
    const int mBase = blockIdx.y * 128, nBase = blockIdx.x * 128;
    u32 sb = (u32)__cvta_generic_to_shared(smem);

    const int g = lane >> 3, rsel = lane & 7;
    const u32 offA = (u32)((wm * 64 + (g & 1) * 8 + rsel) * 80 + (g >> 1) * 16);
    const u32 offB = (u32)((wn * 32 + (g >> 1) * 8 + rsel) * 80 + (g & 1) * 16);

    float acc[4][4][4];
#pragma unroll
    for (int a = 0; a < 4; a++)
#pragma unroll
        for (int b = 0; b < 4; b++)
#pragma unroll
            for (int c = 0; c < 4; c++) acc[a][b][c] = 0.f;

    const int niter = K >> 5;

    auto load_stage = [&](int stage, int kc) {
        u32 st = sb + (u32)stage * GST;
#pragma unroll
        for (int i = 0; i < 2; i++) {
            int ch = i * 256 + tid;              // 0..511
            int row = ch >> 2, c = ch & 3;
            u32 d = st + (u32)(row * 80 + c * 16);
            cpa16(d,         Ahp + (size_t)(mBase + row) * K + kc * 32 + c * 8);
            cpa16(d + 10240, Bhp + (size_t)(nBase + row) * K + kc * 32 + c * 8);
        }
        asm volatile("cp.async.commit_group;" ::: "memory");
    };

    load_stage(0, 0);
    load_stage(1, 1);

    for (int it = 0; it < niter; it++) {
        if (it + 1 < niter) {
            asm volatile("cp.async.wait_group 1;" ::: "memory");
        } else {
            asm volatile("cp.async.wait_group 0;" ::: "memory");
        }
        __syncthreads();
        if (it + 2 < niter) load_stage((it + 2) % 3, it + 2);

        u32 st = sb + (u32)(it % 3) * GST;
#pragma unroll
        for (int ks = 0; ks < 2; ks++) {
            u32 ah[4][4], bh[4][2];
#pragma unroll
            for (int mi = 0; mi < 4; mi++)
                ldsm4(ah[mi], st + offA + (u32)(mi * 16 * 80 + ks * 32));
#pragma unroll
            for (int nh = 0; nh < 2; nh++) {
                u32 t[4];
                ldsm4(t, st + 10240 + offB + (u32)(nh * 16 * 80 + ks * 32));
                bh[2 * nh][0] = t[0]; bh[2 * nh][1] = t[1];
                bh[2 * nh + 1][0] = t[2]; bh[2 * nh + 1][1] = t[3];
            }
#pragma unroll
            for (int mi = 0; mi < 4; mi++)
#pragma unroll
                for (int ni = 0; ni < 4; ni++)
                    mma_f16(acc[mi][ni], ah[mi], bh[ni]);
        }
    }

    __syncthreads();
    const int qrow = lane >> 2, t2 = (lane & 3) * 2;

    if (mode == 0) {
#pragma unroll
        for (int mi = 0; mi < 4; mi++) {
            int r0 = mBase + wm * 64 + mi * 16 + qrow;
#pragma unroll
            for (int ni = 0; ni < 4; ni++) {
                int col = nBase + wn * 32 + ni * 8 + t2;
                float b0 = bias[col], b1 = bias[col + 1];
                *(float2*)&C[(size_t)r0 * N + col] =
                    make_float2(acc[mi][ni][0] + b0, acc[mi][ni][1] + b1);
                *(float2*)&C[(size_t)(r0 + 8) * N + col] =
                    make_float2(acc[mi][ni][2] + b0, acc[mi][ni][3] + b1);
            }
        }
    } else {
        // fused QKV epilogue.  N window type within the 384-col head block:
        const int type = (nBase >> 7) % 3;     // 0=q, 1=k, 2=v
        const int h = nBase / 384;
        const bool rot = (wn == 0) && (type < 2);  // cols [0,32) of q/k: RoPE
        float invf[4];
        if (rot) {
            const float cexp = 9.210340371976184f / 16.0f;  // ln(10000)/16
            invf[0] = expf(-(float)(t2)     * cexp);
            invf[1] = expf(-(float)(t2 + 1) * cexp);
            invf[2] = expf(-(float)(t2 + 8) * cexp);
            invf[3] = expf(-(float)(t2 + 9) * cexp);
        }
        __half* outp = (type == 0) ? qout : ((type == 1) ? kout : vout);
        const float sc = (type == 0) ? 0.08838834764831843f : 1.0f;
#pragma unroll
        for (int mi = 0; mi < 4; mi++) {
#pragma unroll
            for (int rr = 0; rr < 2; rr++) {
                int row = mBase + wm * 64 + mi * 16 + qrow + rr * 8;
                int b = row >> 11, s = row & 2047;
                float vals[8];
#pragma unroll
                for (int ni = 0; ni < 4; ni++) {
                    int col = nBase + wn * 32 + ni * 8 + t2;
                    vals[2 * ni]     = acc[mi][ni][2 * rr]     + bias[col];
                    vals[2 * ni + 1] = acc[mi][ni][2 * rr + 1] + bias[col + 1];
                }
                if (rot) {
                    float sn, cs;
#pragma unroll
                    for (int j = 0; j < 2; j++) {
                        sincosf((float)s * invf[j], &sn, &cs);
                        float lo = vals[j], hi = vals[4 + j];
                        vals[j]     = lo * cs - hi * sn;
                        vals[4 + j] = hi * cs + lo * sn;
                        sincosf((float)s * invf[2 + j], &sn, &cs);
                        float lo2 = vals[2 + j], hi2 = vals[6 + j];
                        vals[2 + j] = lo2 * cs - hi2 * sn;
                        vals[6 + j] = hi2 * cs + lo2 * sn;
                    }
                }
                size_t ob = ((size_t)(b * 16 + h) * SEQ + s) * 128 + wn * 32 + t2;
#pragma unroll
                for (int ni = 0; ni < 4; ni++) {
                    __half2 hv = __floats2half2_rn(vals[2 * ni] * sc,
                                                   vals[2 * ni + 1] * sc);
                    *(__half2*)(outp + ob + ni * 8) = hv;
                }
            }
        }
    }
}

// ---------------------------------------------------------------------------
// Flash attention via mma.sync, single fp16, causal, no-max softmax.
// BQ=128 (8 warps x 16 rows), BKV=64 processed in two 32-col halves to cut
// register pressure (sacc 16 regs) -> 2 CTAs/SM.
// Q resident (34816B); KV stages 34816B each; 104448B/CTA, 2 CTAs/SM.
// Output written single fp16 into g_ah (out-proj A operand), [b*s][2048].
// ---------------------------------------------------------------------------
#define FKV 34816
#define FL_SMEM (34816 + 2 * FKV)

__global__ __launch_bounds__(256, 2)
void flash_mma(const __half* __restrict__ qhp, const __half* __restrict__ khp,
               const __half* __restrict__ vhp, __half* __restrict__ oh)
{
    extern __shared__ __align__(16) char smem[];
    const int tid = threadIdx.x, lane = tid & 31, warp = tid >> 5;
    const int qi = 15 - (int)blockIdx.x;        // heavy q-tiles first
    const int bh = blockIdx.y;
    const int q0 = qi << 7;
    const int nkv = 2 * qi + 2;
    u32 sb = (u32)__cvta_generic_to_shared(smem);

    const int g = lane >> 3, rsel = lane & 7;
    const size_t base = (size_t)bh * SEQ * 128;

    // ---- Q loads (resident @0) ----
#pragma unroll
    for (int i = 0; i < 8; i++) {
        int idx = i * 256 + tid;                 // 0..2047
        int row = idx >> 4, c = idx & 15;
        cpa16(sb + (u32)(row * 272 + c * 16),
              qhp + base + (size_t)(q0 + row) * 128 + c * 8);
    }
    asm volatile("cp.async.commit_group;" ::: "memory");

    auto load_kv = [&](int kt) {
        u32 st = sb + (u32)(34816 + (kt & 1) * FKV);
        const size_t rb = base + (size_t)(kt * 64) * 128;
#pragma unroll
        for (int i = 0; i < 2; i++) {
            int idx = i * 256 + tid;             // 0..511
            int row = idx >> 3, c = idx & 7;     // 64 rows x 8 chunks of 16 cols
            u32 d = st + (u32)(row * 272 + c * 32);
            size_t s = rb + (size_t)row * 128 + c * 16;
            cpa16(d,          khp + s);
            cpa16(d + 16,     khp + s + 8);
            cpa16(d + 17408,      vhp + s);
            cpa16(d + 17408 + 16, vhp + s + 8);
        }
        asm volatile("cp.async.commit_group;" ::: "memory");
    };

    load_kv(0);

    float oacc[16][4];
#pragma unroll
    for (int i = 0; i < 16; i++)
#pragma unroll
        for (int j = 0; j < 4; j++) oacc[i][j] = 0.f;
    float lsum0 = 0.f, lsum1 = 0.f;

    const u32 qoff = sb + (u32)((warp * 16 + (g & 1) * 8 + rsel) * 272 + (g >> 1) * 16);
    const int rowq = warp * 16 + (lane >> 2);        // local q row (of pair)

    for (int kt = 0; kt < nkv; kt++) {
        asm volatile("cp.async.wait_group 0;" ::: "memory");
        __syncthreads();
        if (kt + 1 < nkv) load_kv(kt + 1);
        u32 st = sb + (u32)(34816 + (kt & 1) * FKV);

        const u32 kb = st + (u32)(((g >> 1) * 8 + rsel) * 272 + (g & 1) * 16);
        const u32 vbase = st + 17408 + (u32)(((g & 1) * 8 + rsel) * 272 + (g >> 1) * 16);
        const bool diag = (kt >= 2 * qi);
        const int row0 = q0 + rowq;

        // process this KV tile in two 32-column halves (register diet)
#pragma unroll
        for (int half = 0; half < 2; half++) {
            // ---- S = Q K^T (32 cols) ----
            float sacc[4][4];
#pragma unroll
            for (int i = 0; i < 4; i++)
#pragma unroll
                for (int j = 0; j < 4; j++) sacc[i][j] = 0.f;

            const u32 kbh = kb + (u32)(half * 32 * 272);
#pragma unroll
            for (int ks = 0; ks < 8; ks++) {
                u32 qh4[4];
                ldsm4(qh4, qoff + ks * 32);
                u32 tb0[4], tb1[4];
                ldsm4(tb0, kbh + ks * 32);
                ldsm4(tb1, kbh + 16 * 272 + ks * 32);
                mma_f16(sacc[0], qh4, tb0);
                mma_f16(sacc[1], qh4, tb0 + 2);
                mma_f16(sacc[2], qh4, tb1);
                mma_f16(sacc[3], qh4, tb1 + 2);
            }

            // ---- softmax numerator ----
            const int colb = kt * 64 + half * 32 + 2 * (lane & 3);
            u32 pah[2][4];
#pragma unroll
            for (int ni = 0; ni < 4; ni++) {
                int c0 = colb + ni * 8;
                float p0, p1, p2, p3;
                if (diag) {
                    p0 = (c0     <= row0    ) ? fexp(sacc[ni][0]) : 0.f;
                    p1 = (c0 + 1 <= row0    ) ? fexp(sacc[ni][1]) : 0.f;
                    p2 = (c0     <= row0 + 8) ? fexp(sacc[ni][2]) : 0.f;
                    p3 = (c0 + 1 <= row0 + 8) ? fexp(sacc[ni][3]) : 0.f;
                } else {
                    p0 = fexp(sacc[ni][0]); p1 = fexp(sacc[ni][1]);
                    p2 = fexp(sacc[ni][2]); p3 = fexp(sacc[ni][3]);
                }
                lsum0 += p0 + p1;
                lsum1 += p2 + p3;
                int kt2 = ni >> 1, j = (ni & 1) * 2;
                __half2 h0 = __floats2half2_rn(p0, p1);
                __half2 h1 = __floats2half2_rn(p2, p3);
                pah[kt2][j]     = *(u32*)&h0;
                pah[kt2][j + 1] = *(u32*)&h1;
            }

            // ---- O += P V (32 kv rows) ----
            const u32 vbh = vbase + (u32)(half * 32 * 272);
#pragma unroll
            for (int kt2 = 0; kt2 < 2; kt2++) {
#pragma unroll
                for (int dgp = 0; dgp < 4; dgp++) {
                    u32 th0[4], th1[4];
                    u32 vbb = vbh + kt2 * (16 * 272) + dgp * 64;
                    ldsm4t(th0, vbb);
                    ldsm4t(th1, vbb + 32);
                    mma_f16(oacc[4 * dgp],     pah[kt2], th0);
                    mma_f16(oacc[4 * dgp + 1], pah[kt2], th0 + 2);
                    mma_f16(oacc[4 * dgp + 2], pah[kt2], th1);
                    mma_f16(oacc[4 * dgp + 3], pah[kt2], th1 + 2);
                }
            }
        }
    }

    // ---- normalize + fp16 store into g_ah (out-proj A) ----
    lsum0 += __shfl_xor_sync(0xffffffffu, lsum0, 1);
    lsum0 += __shfl_xor_sync(0xffffffffu, lsum0, 2);
    lsum1 += __shfl_xor_sync(0xffffffffu, lsum1, 1);
    lsum1 += __shfl_xor_sync(0xffffffffu, lsum1, 2);
    float inv0 = 1.f / lsum0, inv1 = 1.f / lsum1;

    const int b = bh >> 4, h = bh & 15;
    const int r0 = q0 + rowq;
    size_t obase0 = ((size_t)(b * SEQ + r0)) * HID + h * 128;
    size_t obase1 = obase0 + (size_t)8 * HID;
#pragma unroll
    for (int dt = 0; dt < 16; dt++) {
        int col = dt * 8 + 2 * (lane & 3);
        __half2 h0 = __floats2half2_rn(oacc[dt][0] * inv0, oacc[dt][1] * inv0);
        __half2 h1 = __floats2half2_rn(oacc[dt][2] * inv1, oacc[dt][3] * inv1);
        *(u32*)(oh + obase0 + col) = *(u32*)&h0;
        *(u32*)(oh + obase1 + col) = *(u32*)&h1;
    }
}

// ---------------------------------------------------------------------------
extern "C" void kernel_launch(void* const* d_in, const int* in_sizes, int n_in,
                              void* d_out, int out_size)
{
    const float* hidden = (const float*)d_in[0];
    const float* qkvk = (const float*)d_in[2];
    const float* qkvb = (const float*)d_in[3];
    const float* outk = (const float*)d_in[4];
    const float* outb = (const float*)d_in[5];
    float* out = (float*)d_out;

    __half *pqh, *pkh, *pvh, *pah, *pbh;
    cudaGetSymbolAddress((void**)&pqh, g_qh);
    cudaGetSymbolAddress((void**)&pkh, g_kh);
    cudaGetSymbolAddress((void**)&pvh, g_vh);
    cudaGetSymbolAddress((void**)&pah, g_ah);
    cudaGetSymbolAddress((void**)&pbh, g_bh);

    cudaFuncSetAttribute((const void*)gemm_mma,
                         cudaFuncAttributeMaxDynamicSharedMemorySize, 3 * GST);
    cudaFuncSetAttribute((const void*)flash_mma,
                         cudaFuncAttributeMaxDynamicSharedMemorySize, FL_SMEM);

    // --- QKV projection + fused RoPE/fp16 epilogue ---
    conv_rm<<<(4096 * 2048 / 4 + 255) / 256, 256>>>((const float4*)hidden, pah, 4096 * 2048 / 4);
    tsplit<<<dim3(6144 / 32, 2048 / 32), dim3(32, 8)>>>(qkvk, pbh, 2048, 6144);
    gemm_mma<<<dim3(48, 32), 256, 3 * GST>>>(pah, pbh, qkvb, nullptr,
                                             4096, 6144, 2048, 1, pqh, pkh, pvh);

    // --- causal flash attention (single-fp16 HMMA, 2 CTAs/SM), writes out-proj A ---
    flash_mma<<<dim3(16, 32), 256, FL_SMEM>>>(pqh, pkh, pvh, pah);

    // --- output projection: [4096,2048] @ [2048,2048] + bias ---
    tsplit<<<dim3(2048 / 32, 2048 / 32), dim3(32, 8)>>>(outk, pbh, 2048, 2048);
    gemm_mma<<<dim3(16, 32), 256, 3 * GST>>>(pah, pbh, outb, out,
                                             4096, 2048, 2048, 0, nullptr, nullptr, nullptr);
}